// round 1
// baseline (speedup 1.0000x reference)
#include <cuda_runtime.h>
#include <cstdint>

#define NB    2048
#define DIN   768
#define DOUT  768
#define DICTN 24576
#define K1    32
#define K2    512

#define S_OFS  (NB*DOUT)                      /* 1,572,864  */
#define SC_OFS (S_OFS + NB*DICTN)             /* 51,904,512 */

// ------------------------- scratch (device globals) -------------------------
__device__ float g_acts[(size_t)NB*DICTN];    // 201 MB, exact fp32 relu(x_enc @ W_enc)
__device__ float g_xe[NB*DIN];
__device__ float g_yn[NB*DOUT];
__device__ float g_ymean[NB];
__device__ float g_ystd[NB];
__device__ float g_v32[NB*K1];
__device__ int   g_i32[NB*K1];
__device__ float g_rowl1[NB];
__device__ float g_rowl0[NB];
__device__ float g_rowl2[NB];
__device__ float g_rowaux[NB];
__device__ int   g_colact[DICTN];
__device__ int   g_dead[DICTN];
__device__ int   g_numdead;
__device__ int   g_deadany;
__device__ float g_vaux[(size_t)NB*K2];
__device__ int   g_iaux[(size_t)NB*K2];
__device__ int   g_cntaux[NB];

// ------------------------------- init ---------------------------------------
__global__ void k_init() {
    int i = blockIdx.x*blockDim.x + threadIdx.x;
    if (i < DICTN) g_colact[i] = 0;
    if (i == 0) { g_numdead = 0; g_deadany = 0; }
}

// --------------------------- row normalization ------------------------------
// xn = (x - mean)/(std_ddof1 + 1e-5); x_enc = xn - b_dec; same for y (+ keep m, s)
__global__ void k_norm(const float* __restrict__ x, const float* __restrict__ y,
                       const float* __restrict__ bdec) {
    int r = blockIdx.x, t = threadIdx.x;
    __shared__ float red[256];

    // ---- x ----
    float x0 = x[r*DIN + t], x1 = x[r*DIN + t + 256], x2 = x[r*DIN + t + 512];
    red[t] = x0 + x1 + x2; __syncthreads();
    for (int o = 128; o > 0; o >>= 1) { if (t < o) red[t] += red[t+o]; __syncthreads(); }
    float m = red[0] * (1.0f/DIN);
    __syncthreads();
    float d0 = x0 - m, d1 = x1 - m, d2 = x2 - m;
    red[t] = d0*d0 + d1*d1 + d2*d2; __syncthreads();
    for (int o = 128; o > 0; o >>= 1) { if (t < o) red[t] += red[t+o]; __syncthreads(); }
    float s = sqrtf(red[0] * (1.0f/(DIN-1)));
    __syncthreads();
    float inv = 1.0f/(s + 1e-5f);
    g_xe[r*DIN + t]       = d0*inv - bdec[t];
    g_xe[r*DIN + t + 256] = d1*inv - bdec[t+256];
    g_xe[r*DIN + t + 512] = d2*inv - bdec[t+512];

    // ---- y ----
    float y0 = y[r*DOUT + t], y1 = y[r*DOUT + t + 256], y2 = y[r*DOUT + t + 512];
    red[t] = y0 + y1 + y2; __syncthreads();
    for (int o = 128; o > 0; o >>= 1) { if (t < o) red[t] += red[t+o]; __syncthreads(); }
    float my = red[0] * (1.0f/DOUT);
    __syncthreads();
    float e0 = y0 - my, e1 = y1 - my, e2 = y2 - my;
    red[t] = e0*e0 + e1*e1 + e2*e2; __syncthreads();
    for (int o = 128; o > 0; o >>= 1) { if (t < o) red[t] += red[t+o]; __syncthreads(); }
    float sy = sqrtf(red[0] * (1.0f/(DOUT-1)));
    __syncthreads();
    float invy = 1.0f/(sy + 1e-5f);
    g_yn[r*DOUT + t]       = e0*invy;
    g_yn[r*DOUT + t + 256] = e1*invy;
    g_yn[r*DOUT + t + 512] = e2*invy;
    if (t == 0) { g_ymean[r] = my; g_ystd[r] = sy; }
}

// ------------------------------ fp32 GEMM -----------------------------------
// acts[2048,24576] = relu(x_enc[2048,768] @ W_enc[768,24576]); packed f32x2 FMA.
#define BM 128
#define BN 128
#define BK 16

__device__ __forceinline__ unsigned long long pk2(float a, float b) {
    unsigned long long r;
    asm("mov.b64 %0, {%1, %2};" : "=l"(r) : "f"(a), "f"(b));
    return r;
}
__device__ __forceinline__ void fma2(unsigned long long &c, unsigned long long a,
                                     unsigned long long b) {
    asm("fma.rn.f32x2 %0, %1, %2, %3;" : "=l"(c) : "l"(a), "l"(b), "l"(c));
}

__global__ void __launch_bounds__(256) k_gemm(const float* __restrict__ W) {
    __shared__ float As[2][BK][BM];
    __shared__ float Bs[2][BK][BN];
    int tid  = threadIdx.x;
    int m0   = blockIdx.y * BM, n0 = blockIdx.x * BN;
    int arow = tid >> 2,  acol = (tid & 3) << 2;
    int brow = tid >> 5,  bcol = (tid & 31) << 2;
    int mrow = (tid >> 4) << 3, ncol = (tid & 15) << 3;

    unsigned long long c[8][4];
#pragma unroll
    for (int i = 0; i < 8; i++)
#pragma unroll
        for (int j = 0; j < 4; j++) c[i][j] = 0ull;

    float4 fa0 = *(const float4*)(g_xe + (m0+arow)*DIN + acol);
    float4 fa1 = *(const float4*)(g_xe + (m0+arow+64)*DIN + acol);
    float4 fb0 = *(const float4*)(W + (size_t)brow*DICTN + n0 + bcol);
    float4 fb1 = *(const float4*)(W + (size_t)(brow+8)*DICTN + n0 + bcol);
    As[0][acol+0][arow] = fa0.x; As[0][acol+1][arow] = fa0.y;
    As[0][acol+2][arow] = fa0.z; As[0][acol+3][arow] = fa0.w;
    As[0][acol+0][arow+64] = fa1.x; As[0][acol+1][arow+64] = fa1.y;
    As[0][acol+2][arow+64] = fa1.z; As[0][acol+3][arow+64] = fa1.w;
    *(float4*)&Bs[0][brow][bcol]   = fb0;
    *(float4*)&Bs[0][brow+8][bcol] = fb1;
    __syncthreads();

    const int NT = DIN / BK;   // 48
    int cur = 0;
    for (int ts = 0; ts < NT; ++ts) {
        int nxt = cur ^ 1;
        if (ts + 1 < NT) {
            int k0 = (ts + 1) * BK;
            fa0 = *(const float4*)(g_xe + (m0+arow)*DIN + k0 + acol);
            fa1 = *(const float4*)(g_xe + (m0+arow+64)*DIN + k0 + acol);
            fb0 = *(const float4*)(W + (size_t)(k0+brow)*DICTN + n0 + bcol);
            fb1 = *(const float4*)(W + (size_t)(k0+brow+8)*DICTN + n0 + bcol);
        }
#pragma unroll
        for (int kk = 0; kk < BK; ++kk) {
            float4 a0 = *(const float4*)&As[cur][kk][mrow];
            float4 a1 = *(const float4*)&As[cur][kk][mrow+4];
            ulonglong2 b01 = *(const ulonglong2*)&Bs[cur][kk][ncol];
            ulonglong2 b23 = *(const ulonglong2*)&Bs[cur][kk][ncol+4];
            unsigned long long bb0 = b01.x, bb1 = b01.y, bb2 = b23.x, bb3 = b23.y;
            float av[8] = {a0.x, a0.y, a0.z, a0.w, a1.x, a1.y, a1.z, a1.w};
#pragma unroll
            for (int i = 0; i < 8; i++) {
                unsigned long long aa = pk2(av[i], av[i]);
                fma2(c[i][0], aa, bb0);
                fma2(c[i][1], aa, bb1);
                fma2(c[i][2], aa, bb2);
                fma2(c[i][3], aa, bb3);
            }
        }
        if (ts + 1 < NT) {
            As[nxt][acol+0][arow] = fa0.x; As[nxt][acol+1][arow] = fa0.y;
            As[nxt][acol+2][arow] = fa0.z; As[nxt][acol+3][arow] = fa0.w;
            As[nxt][acol+0][arow+64] = fa1.x; As[nxt][acol+1][arow+64] = fa1.y;
            As[nxt][acol+2][arow+64] = fa1.z; As[nxt][acol+3][arow+64] = fa1.w;
            *(float4*)&Bs[nxt][brow][bcol]   = fb0;
            *(float4*)&Bs[nxt][brow+8][bcol] = fb1;
            __syncthreads();
        }
        cur = nxt;
    }
#pragma unroll
    for (int i = 0; i < 8; i++) {
        float* orow = g_acts + (size_t)(m0+mrow+i)*DICTN + n0 + ncol;
        float4 o0, o1;
        o0.x = fmaxf(__uint_as_float((unsigned)(c[i][0]       )), 0.f);
        o0.y = fmaxf(__uint_as_float((unsigned)(c[i][0] >> 32 )), 0.f);
        o0.z = fmaxf(__uint_as_float((unsigned)(c[i][1]       )), 0.f);
        o0.w = fmaxf(__uint_as_float((unsigned)(c[i][1] >> 32 )), 0.f);
        o1.x = fmaxf(__uint_as_float((unsigned)(c[i][2]       )), 0.f);
        o1.y = fmaxf(__uint_as_float((unsigned)(c[i][2] >> 32 )), 0.f);
        o1.z = fmaxf(__uint_as_float((unsigned)(c[i][3]       )), 0.f);
        o1.w = fmaxf(__uint_as_float((unsigned)(c[i][3] >> 32 )), 0.f);
        *(float4*)orow     = o0;
        *(float4*)(orow+4) = o1;
    }
}

// --------------------------- top-32 per row ---------------------------------
// MSD radix select on float bit patterns (all values >= 0 -> bits monotone).
__global__ void k_top32() {
    int r = blockIdx.x, t = threadIdx.x;
    const float* __restrict__ row = g_acts + (size_t)r*DICTN;
    __shared__ unsigned int hist[256];
    __shared__ unsigned int sT;
    __shared__ int sRem, sCnt, sTc, sTaken;
    __shared__ float sval[K1];
    __shared__ int   sidx[K1];
    __shared__ int   tiebuf[64];
    __shared__ float red[256];

    if (t == 0) { sT = 0u; sRem = K1; }
    __syncthreads();
    for (int pass = 0; pass < 4; ++pass) {
        int shift = 24 - 8*pass;
        hist[t] = 0u; __syncthreads();
        unsigned int pref = sT;
        for (int j = t; j < DICTN; j += 256) {
            unsigned int k = __float_as_uint(row[j]);
            bool ok = (pass == 0) || (((k ^ pref) >> (shift + 8)) == 0u);
            if (ok) atomicAdd(&hist[(k >> shift) & 255u], 1u);
        }
        __syncthreads();
        if (t == 0) {
            int rem = sRem, b = 255;
            for (;;) {
                int cn = (int)hist[b];
                if (cn >= rem || b == 0) break;
                rem -= cn; --b;
            }
            sRem = rem;
            sT = pref | ((unsigned int)b << shift);
        }
        __syncthreads();
    }
    unsigned int T = sT;
    int need = sRem;
    if (t == 0) { sCnt = 0; sTc = 0; }
    __syncthreads();
    float myl1 = 0.f, myl0 = 0.f;
    for (int j = t; j < DICTN; j += 256) {
        float v = row[j];
        unsigned int k = __float_as_uint(v);
        if (k > T) {
            int p = atomicAdd(&sCnt, 1);
            sval[p] = v; sidx[p] = j;
            myl1 += v; myl0 += 1.f;
        } else if (T != 0u && k == T) {
            int p = atomicAdd(&sTc, 1);
            if (p < 64) tiebuf[p] = j;
        }
    }
    __syncthreads();
    int G = sCnt;
    if (t == 0) {
        int tc = sTc < 64 ? sTc : 64;
        int taken = 0;
        if (T != 0u) {
            int want = need < tc ? need : tc;
            for (int q = 0; q < want; ++q) {         // lowest-index ties (JAX tie-break)
                int best = 0x7fffffff, bi = -1;
                for (int u = 0; u < tc; ++u) {
                    int id = tiebuf[u];
                    if (id >= 0 && id < best) { best = id; bi = u; }
                }
                tiebuf[bi] = -1;
                sval[G+q] = __uint_as_float(T);
                sidx[G+q] = best;
            }
            taken = want;
        }
        for (int q = G + taken; q < K1; ++q) { sval[q] = 0.f; sidx[q] = -1; }
        sTaken = taken;
    }
    __syncthreads();
    red[t] = myl1; __syncthreads();
    for (int o = 128; o > 0; o >>= 1) { if (t < o) red[t] += red[t+o]; __syncthreads(); }
    if (t == 0) g_rowl1[r] = red[0] + (float)sTaken * __uint_as_float(T);
    __syncthreads();
    red[t] = myl0; __syncthreads();
    for (int o = 128; o > 0; o >>= 1) { if (t < o) red[t] += red[t+o]; __syncthreads(); }
    if (t == 0) g_rowl0[r] = red[0] + (float)sTaken;
    __syncthreads();
    if (t < K1) {
        g_v32[r*K1 + t] = sval[t];
        g_i32[r*K1 + t] = sidx[t];
        if (sval[t] > 0.f) g_colact[sidx[t]] = 1;
    }
}

// ----------------------- dead-feature bookkeeping ---------------------------
__global__ void k_dead(const float* __restrict__ nb) {
    int c = blockIdx.x*256 + threadIdx.x;
    float nbn = g_colact[c] ? 0.f : nb[c] + 1.f;
    int dead = (nbn >= 100.f) ? 1 : 0;
    g_dead[c] = dead;
    if (dead) atomicOr(&g_deadany, 1);
    if (nbn > 100.f) atomicAdd(&g_numdead, 1);
}

// --------------------- aux top-512 per row (dead mask) ----------------------
__global__ void k_aux() {
    int r = blockIdx.x, t = threadIdx.x;
    const float* __restrict__ row = g_acts + (size_t)r*DICTN;
    __shared__ unsigned int hist[256];
    __shared__ unsigned int sT;
    __shared__ int sRem, sCnt, sTc;
    __shared__ int tiebuf[256];

    if (t == 0) { sT = 0u; sRem = K2; }
    __syncthreads();
    for (int pass = 0; pass < 4; ++pass) {
        int shift = 24 - 8*pass;
        hist[t] = 0u; __syncthreads();
        unsigned int pref = sT;
        for (int j = t; j < DICTN; j += 256) {
            unsigned int k = g_dead[j] ? __float_as_uint(row[j]) : 0u;
            bool ok = (pass == 0) || (((k ^ pref) >> (shift + 8)) == 0u);
            if (ok) atomicAdd(&hist[(k >> shift) & 255u], 1u);
        }
        __syncthreads();
        if (t == 0) {
            int rem = sRem, b = 255;
            for (;;) {
                int cn = (int)hist[b];
                if (cn >= rem || b == 0) break;
                rem -= cn; --b;
            }
            sRem = rem;
            sT = pref | ((unsigned int)b << shift);
        }
        __syncthreads();
    }
    unsigned int T = sT;
    int need = sRem;
    if (t == 0) { sCnt = 0; sTc = 0; }
    __syncthreads();
    for (int j = t; j < DICTN; j += 256) {
        float v = row[j];
        unsigned int k = g_dead[j] ? __float_as_uint(v) : 0u;
        if (k > T) {
            int p = atomicAdd(&sCnt, 1);
            g_vaux[(size_t)r*K2 + p] = v;
            g_iaux[(size_t)r*K2 + p] = j;
        } else if (T != 0u && k == T) {
            int p = atomicAdd(&sTc, 1);
            if (p < 256) tiebuf[p] = j;
        }
    }
    __syncthreads();
    if (t == 0) {
        int G = sCnt;
        int tc = sTc < 256 ? sTc : 256;
        int taken = 0;
        if (T != 0u) {
            int want = need < tc ? need : tc;
            for (int q = 0; q < want; ++q) {
                int best = 0x7fffffff, bi = -1;
                for (int u = 0; u < tc; ++u) {
                    int id = tiebuf[u];
                    if (id >= 0 && id < best) { best = id; bi = u; }
                }
                tiebuf[bi] = -1;
                g_vaux[(size_t)r*K2 + G + q] = __uint_as_float(T);
                g_iaux[(size_t)r*K2 + G + q] = best;
            }
            taken = want;
        }
        g_cntaux[r] = G + taken;
    }
}

// ---------------------- zero + scatter acts_sparse --------------------------
__global__ void k_zero(float* __restrict__ p) {
    size_t i  = (size_t)blockIdx.x*blockDim.x + threadIdx.x;
    size_t n4 = (size_t)NB*DICTN/4;
    float4 z = {0.f, 0.f, 0.f, 0.f};
    for (size_t j = i; j < n4; j += (size_t)gridDim.x*blockDim.x)
        ((float4*)p)[j] = z;
}
__global__ void k_scatter(float* __restrict__ p) {
    int i = blockIdx.x*256 + threadIdx.x;
    if (i >= NB*K1) return;
    int r = i / K1;
    int id = g_i32[i];
    if (id >= 0) p[(size_t)r*DICTN + id] = g_v32[i];
}

// ------------------------ decode + per-row losses ---------------------------
__global__ void k_decode(const float* __restrict__ Wd, const float* __restrict__ bdec,
                         float* __restrict__ outy) {
    int r = blockIdx.x, t = threadIdx.x;
    __shared__ float sv[K1]; __shared__ int si[K1];
    __shared__ float av[K2]; __shared__ int ai[K2];
    __shared__ float red[256];
    if (t < K1) { sv[t] = g_v32[r*K1 + t]; si[t] = g_i32[r*K1 + t]; }
    int cnt = g_cntaux[r];
    for (int q = t; q < cnt; q += 256) {
        av[q] = g_vaux[(size_t)r*K2 + q];
        ai[q] = g_iaux[(size_t)r*K2 + q];
    }
    __syncthreads();
    float ymean = g_ymean[r], ystd = g_ystd[r];
    float l2p = 0.f, auxp = 0.f;
    for (int d = t; d < DOUT; d += 256) {
        float yp = bdec[d];
#pragma unroll
        for (int q = 0; q < K1; q++) {
            int id = si[q];
            if (id >= 0) yp += sv[q] * Wd[(size_t)id*DOUT + d];
        }
        float ynv = g_yn[r*DOUT + d];
        outy[(size_t)r*DOUT + d] = yp*ystd + ymean;
        float e = yp - ynv;
        l2p += e*e;
        float ya0 = 0.f, ya1 = 0.f;
        int q = 0;
        for (; q + 1 < cnt; q += 2) {
            ya0 += av[q]   * Wd[(size_t)ai[q]  *DOUT + d];
            ya1 += av[q+1] * Wd[(size_t)ai[q+1]*DOUT + d];
        }
        if (q < cnt) ya0 += av[q] * Wd[(size_t)ai[q]*DOUT + d];
        float ea = (ya0 + ya1) - (ynv - yp);
        auxp += ea*ea;
    }
    red[t] = l2p; __syncthreads();
    for (int o = 128; o > 0; o >>= 1) { if (t < o) red[t] += red[t+o]; __syncthreads(); }
    if (t == 0) g_rowl2[r] = red[0];
    __syncthreads();
    red[t] = auxp; __syncthreads();
    for (int o = 128; o > 0; o >>= 1) { if (t < o) red[t] += red[t+o]; __syncthreads(); }
    if (t == 0) g_rowaux[r] = red[0];
}

// ------------------------------ finalize -------------------------------------
__global__ void k_final(float* __restrict__ outsc) {
    int t = threadIdx.x;
    __shared__ float red[256];
    __shared__ float res[4];
    const float* arrs[4] = { g_rowl2, g_rowaux, g_rowl1, g_rowl0 };
    for (int a = 0; a < 4; a++) {
        float s = 0.f;
        for (int j = t; j < NB; j += 256) s += arrs[a][j];
        red[t] = s; __syncthreads();
        for (int o = 128; o > 0; o >>= 1) { if (t < o) red[t] += red[t+o]; __syncthreads(); }
        if (t == 0) res[a] = red[0];
        __syncthreads();
    }
    if (t == 0) {
        float l2   = res[0] / (float)(NB*DOUT);
        float auxm = res[1] / (float)(NB*DOUT);
        float l1n  = res[2] / (float)NB;
        float l0   = res[3] / (float)NB;
        float l1l  = 0.001f * l1n;
        float aux  = g_deadany ? 0.03125f * auxm : 0.f;
        outsc[0] = l2 + l1l + aux;   // loss
        outsc[1] = l2;               // l2_loss
        outsc[2] = l1l;              // l1_loss
        outsc[3] = l0;               // l0_norm
        outsc[4] = l1n;              // l1_norm
        outsc[5] = aux;              // aux_loss
        outsc[6] = (float)g_numdead; // num_dead_features
    }
}

// ------------------------------- launcher ------------------------------------
extern "C" void kernel_launch(void* const* d_in, const int* in_sizes, int n_in,
                              void* d_out, int out_size) {
    (void)in_sizes; (void)n_in; (void)out_size;
    const float* x  = (const float*)d_in[0];   // x_in
    const float* y  = (const float*)d_in[1];   // y_target
    const float* nb = (const float*)d_in[2];   // num_batches_not_active
    const float* We = (const float*)d_in[3];   // W_enc [768, 24576]
    const float* Wd = (const float*)d_in[4];   // W_dec [24576, 768]
    const float* bd = (const float*)d_in[5];   // b_dec [768]
    float* out = (float*)d_out;

    k_init   <<<DICTN/256, 256>>>();
    k_norm   <<<NB, 256>>>(x, y, bd);
    k_gemm   <<<dim3(DICTN/BN, NB/BM), 256>>>(We);
    k_top32  <<<NB, 256>>>();
    k_dead   <<<DICTN/256, 256>>>(nb);
    k_aux    <<<NB, 256>>>();
    k_zero   <<<4096, 256>>>(out + S_OFS);
    k_scatter<<<(NB*K1)/256, 256>>>(out + S_OFS);
    k_decode <<<NB, 256>>>(Wd, bd, out);
    k_final  <<<1, 256>>>(out + SC_OFS);
}

// round 2
// speedup vs baseline: 1.0005x; 1.0005x over previous
#include <cuda_runtime.h>
#include <cstdint>

#define NB    2048
#define DIN   768
#define DOUT  768
#define DICTN 24576
#define K1    32
#define K2    512

#define S_OFS  (NB*DOUT)                      /* 1,572,864  */
#define SC_OFS (S_OFS + NB*DICTN)             /* 51,904,512 */

// ------------------------- scratch (device globals) -------------------------
__device__ float g_acts[(size_t)NB*DICTN];    // 201 MB, exact fp32 relu(x_enc @ W_enc)
__device__ float g_xe[NB*DIN];
__device__ float g_yn[NB*DOUT];
__device__ float g_ymean[NB];
__device__ float g_ystd[NB];
__device__ float g_v32[NB*K1];
__device__ int   g_i32[NB*K1];
__device__ float g_rowl1[NB];
__device__ float g_rowl0[NB];
__device__ float g_rowl2[NB];
__device__ float g_rowaux[NB];
__device__ int   g_colact[DICTN];
__device__ int   g_dead[DICTN];
__device__ int   g_numdead;
__device__ int   g_deadany;
__device__ float g_vaux[(size_t)NB*K2];
__device__ int   g_iaux[(size_t)NB*K2];
__device__ int   g_cntaux[NB];

// ------------------------------- init ---------------------------------------
__global__ void k_init() {
    int i = blockIdx.x*blockDim.x + threadIdx.x;
    if (i < DICTN) g_colact[i] = 0;
    if (i == 0) { g_numdead = 0; g_deadany = 0; }
}

// --------------------------- row normalization ------------------------------
// xn = (x - mean)/(std_ddof1 + 1e-5); x_enc = xn - b_dec; same for y (+ keep m, s)
__global__ void k_norm(const float* __restrict__ x, const float* __restrict__ y,
                       const float* __restrict__ bdec) {
    int r = blockIdx.x, t = threadIdx.x;
    __shared__ float red[256];

    // ---- x ----
    float x0 = x[r*DIN + t], x1 = x[r*DIN + t + 256], x2 = x[r*DIN + t + 512];
    red[t] = x0 + x1 + x2; __syncthreads();
    for (int o = 128; o > 0; o >>= 1) { if (t < o) red[t] += red[t+o]; __syncthreads(); }
    float m = red[0] * (1.0f/DIN);
    __syncthreads();
    float d0 = x0 - m, d1 = x1 - m, d2 = x2 - m;
    red[t] = d0*d0 + d1*d1 + d2*d2; __syncthreads();
    for (int o = 128; o > 0; o >>= 1) { if (t < o) red[t] += red[t+o]; __syncthreads(); }
    float s = sqrtf(red[0] * (1.0f/(DIN-1)));
    __syncthreads();
    float inv = 1.0f/(s + 1e-5f);
    g_xe[r*DIN + t]       = d0*inv - bdec[t];
    g_xe[r*DIN + t + 256] = d1*inv - bdec[t+256];
    g_xe[r*DIN + t + 512] = d2*inv - bdec[t+512];

    // ---- y ----
    float y0 = y[r*DOUT + t], y1 = y[r*DOUT + t + 256], y2 = y[r*DOUT + t + 512];
    red[t] = y0 + y1 + y2; __syncthreads();
    for (int o = 128; o > 0; o >>= 1) { if (t < o) red[t] += red[t+o]; __syncthreads(); }
    float my = red[0] * (1.0f/DOUT);
    __syncthreads();
    float e0 = y0 - my, e1 = y1 - my, e2 = y2 - my;
    red[t] = e0*e0 + e1*e1 + e2*e2; __syncthreads();
    for (int o = 128; o > 0; o >>= 1) { if (t < o) red[t] += red[t+o]; __syncthreads(); }
    float sy = sqrtf(red[0] * (1.0f/(DOUT-1)));
    __syncthreads();
    float invy = 1.0f/(sy + 1e-5f);
    g_yn[r*DOUT + t]       = e0*invy;
    g_yn[r*DOUT + t + 256] = e1*invy;
    g_yn[r*DOUT + t + 512] = e2*invy;
    if (t == 0) { g_ymean[r] = my; g_ystd[r] = sy; }
}

// ------------------------------ fp32 GEMM -----------------------------------
// acts[2048,24576] = relu(x_enc[2048,768] @ W_enc[768,24576]); packed f32x2 FMA.
#define BM 128
#define BN 128
#define BK 16

__device__ __forceinline__ unsigned long long pk2(float a, float b) {
    unsigned long long r;
    asm("mov.b64 %0, {%1, %2};" : "=l"(r) : "f"(a), "f"(b));
    return r;
}
__device__ __forceinline__ void fma2(unsigned long long &c, unsigned long long a,
                                     unsigned long long b) {
    asm("fma.rn.f32x2 %0, %1, %2, %3;" : "=l"(c) : "l"(a), "l"(b), "l"(c));
}

__global__ void __launch_bounds__(256) k_gemm(const float* __restrict__ W) {
    __shared__ float As[2][BK][BM];
    __shared__ float Bs[2][BK][BN];
    int tid  = threadIdx.x;
    int m0   = blockIdx.y * BM, n0 = blockIdx.x * BN;
    int arow = tid >> 2,  acol = (tid & 3) << 2;
    int brow = tid >> 5,  bcol = (tid & 31) << 2;
    int mrow = (tid >> 4) << 3, ncol = (tid & 15) << 3;

    unsigned long long c[8][4];
#pragma unroll
    for (int i = 0; i < 8; i++)
#pragma unroll
        for (int j = 0; j < 4; j++) c[i][j] = 0ull;

    float4 fa0 = *(const float4*)(g_xe + (m0+arow)*DIN + acol);
    float4 fa1 = *(const float4*)(g_xe + (m0+arow+64)*DIN + acol);
    float4 fb0 = *(const float4*)(W + (size_t)brow*DICTN + n0 + bcol);
    float4 fb1 = *(const float4*)(W + (size_t)(brow+8)*DICTN + n0 + bcol);
    As[0][acol+0][arow] = fa0.x; As[0][acol+1][arow] = fa0.y;
    As[0][acol+2][arow] = fa0.z; As[0][acol+3][arow] = fa0.w;
    As[0][acol+0][arow+64] = fa1.x; As[0][acol+1][arow+64] = fa1.y;
    As[0][acol+2][arow+64] = fa1.z; As[0][acol+3][arow+64] = fa1.w;
    *(float4*)&Bs[0][brow][bcol]   = fb0;
    *(float4*)&Bs[0][brow+8][bcol] = fb1;
    __syncthreads();

    const int NT = DIN / BK;   // 48
    int cur = 0;
    for (int ts = 0; ts < NT; ++ts) {
        int nxt = cur ^ 1;
        if (ts + 1 < NT) {
            int k0 = (ts + 1) * BK;
            fa0 = *(const float4*)(g_xe + (m0+arow)*DIN + k0 + acol);
            fa1 = *(const float4*)(g_xe + (m0+arow+64)*DIN + k0 + acol);
            fb0 = *(const float4*)(W + (size_t)(k0+brow)*DICTN + n0 + bcol);
            fb1 = *(const float4*)(W + (size_t)(k0+brow+8)*DICTN + n0 + bcol);
        }
#pragma unroll
        for (int kk = 0; kk < BK; ++kk) {
            float4 a0 = *(const float4*)&As[cur][kk][mrow];
            float4 a1 = *(const float4*)&As[cur][kk][mrow+4];
            ulonglong2 b01 = *(const ulonglong2*)&Bs[cur][kk][ncol];
            ulonglong2 b23 = *(const ulonglong2*)&Bs[cur][kk][ncol+4];
            unsigned long long bb0 = b01.x, bb1 = b01.y, bb2 = b23.x, bb3 = b23.y;
            float av[8] = {a0.x, a0.y, a0.z, a0.w, a1.x, a1.y, a1.z, a1.w};
#pragma unroll
            for (int i = 0; i < 8; i++) {
                unsigned long long aa = pk2(av[i], av[i]);
                fma2(c[i][0], aa, bb0);
                fma2(c[i][1], aa, bb1);
                fma2(c[i][2], aa, bb2);
                fma2(c[i][3], aa, bb3);
            }
        }
        if (ts + 1 < NT) {
            As[nxt][acol+0][arow] = fa0.x; As[nxt][acol+1][arow] = fa0.y;
            As[nxt][acol+2][arow] = fa0.z; As[nxt][acol+3][arow] = fa0.w;
            As[nxt][acol+0][arow+64] = fa1.x; As[nxt][acol+1][arow+64] = fa1.y;
            As[nxt][acol+2][arow+64] = fa1.z; As[nxt][acol+3][arow+64] = fa1.w;
            *(float4*)&Bs[nxt][brow][bcol]   = fb0;
            *(float4*)&Bs[nxt][brow+8][bcol] = fb1;
            __syncthreads();
        }
        cur = nxt;
    }
#pragma unroll
    for (int i = 0; i < 8; i++) {
        float* orow = g_acts + (size_t)(m0+mrow+i)*DICTN + n0 + ncol;
        float4 o0, o1;
        o0.x = fmaxf(__uint_as_float((unsigned)(c[i][0]       )), 0.f);
        o0.y = fmaxf(__uint_as_float((unsigned)(c[i][0] >> 32 )), 0.f);
        o0.z = fmaxf(__uint_as_float((unsigned)(c[i][1]       )), 0.f);
        o0.w = fmaxf(__uint_as_float((unsigned)(c[i][1] >> 32 )), 0.f);
        o1.x = fmaxf(__uint_as_float((unsigned)(c[i][2]       )), 0.f);
        o1.y = fmaxf(__uint_as_float((unsigned)(c[i][2] >> 32 )), 0.f);
        o1.z = fmaxf(__uint_as_float((unsigned)(c[i][3]       )), 0.f);
        o1.w = fmaxf(__uint_as_float((unsigned)(c[i][3] >> 32 )), 0.f);
        *(float4*)orow     = o0;
        *(float4*)(orow+4) = o1;
    }
}

// --------------------------- top-32 per row ---------------------------------
// MSD radix select on float bit patterns (all values >= 0 -> bits monotone).
__global__ void k_top32() {
    int r = blockIdx.x, t = threadIdx.x;
    const float* __restrict__ row = g_acts + (size_t)r*DICTN;
    __shared__ unsigned int hist[256];
    __shared__ unsigned int sT;
    __shared__ int sRem, sCnt, sTc, sTaken;
    __shared__ float sval[K1];
    __shared__ int   sidx[K1];
    __shared__ int   tiebuf[64];
    __shared__ float red[256];

    if (t == 0) { sT = 0u; sRem = K1; }
    __syncthreads();
    for (int pass = 0; pass < 4; ++pass) {
        int shift = 24 - 8*pass;
        hist[t] = 0u; __syncthreads();
        unsigned int pref = sT;
        for (int j = t; j < DICTN; j += 256) {
            unsigned int k = __float_as_uint(row[j]);
            bool ok = (pass == 0) || (((k ^ pref) >> (shift + 8)) == 0u);
            if (ok) atomicAdd(&hist[(k >> shift) & 255u], 1u);
        }
        __syncthreads();
        if (t == 0) {
            int rem = sRem, b = 255;
            for (;;) {
                int cn = (int)hist[b];
                if (cn >= rem || b == 0) break;
                rem -= cn; --b;
            }
            sRem = rem;
            sT = pref | ((unsigned int)b << shift);
        }
        __syncthreads();
    }
    unsigned int T = sT;
    int need = sRem;
    if (t == 0) { sCnt = 0; sTc = 0; }
    __syncthreads();
    float myl1 = 0.f, myl0 = 0.f;
    for (int j = t; j < DICTN; j += 256) {
        float v = row[j];
        unsigned int k = __float_as_uint(v);
        if (k > T) {
            int p = atomicAdd(&sCnt, 1);
            sval[p] = v; sidx[p] = j;
            myl1 += v; myl0 += 1.f;
        } else if (T != 0u && k == T) {
            int p = atomicAdd(&sTc, 1);
            if (p < 64) tiebuf[p] = j;
        }
    }
    __syncthreads();
    int G = sCnt;
    if (t == 0) {
        int tc = sTc < 64 ? sTc : 64;
        int taken = 0;
        if (T != 0u) {
            int want = need < tc ? need : tc;
            for (int q = 0; q < want; ++q) {         // lowest-index ties (JAX tie-break)
                int best = 0x7fffffff, bi = -1;
                for (int u = 0; u < tc; ++u) {
                    int id = tiebuf[u];
                    if (id >= 0 && id < best) { best = id; bi = u; }
                }
                tiebuf[bi] = -1;
                sval[G+q] = __uint_as_float(T);
                sidx[G+q] = best;
            }
            taken = want;
        }
        for (int q = G + taken; q < K1; ++q) { sval[q] = 0.f; sidx[q] = -1; }
        sTaken = taken;
    }
    __syncthreads();
    red[t] = myl1; __syncthreads();
    for (int o = 128; o > 0; o >>= 1) { if (t < o) red[t] += red[t+o]; __syncthreads(); }
    if (t == 0) g_rowl1[r] = red[0] + (float)sTaken * __uint_as_float(T);
    __syncthreads();
    red[t] = myl0; __syncthreads();
    for (int o = 128; o > 0; o >>= 1) { if (t < o) red[t] += red[t+o]; __syncthreads(); }
    if (t == 0) g_rowl0[r] = red[0] + (float)sTaken;
    __syncthreads();
    if (t < K1) {
        g_v32[r*K1 + t] = sval[t];
        g_i32[r*K1 + t] = sidx[t];
        if (sval[t] > 0.f) g_colact[sidx[t]] = 1;
    }
}

// ----------------------- dead-feature bookkeeping ---------------------------
__global__ void k_dead(const float* __restrict__ nb) {
    int c = blockIdx.x*256 + threadIdx.x;
    float nbn = g_colact[c] ? 0.f : nb[c] + 1.f;
    int dead = (nbn >= 100.f) ? 1 : 0;
    g_dead[c] = dead;
    if (dead) atomicOr(&g_deadany, 1);
    if (nbn > 100.f) atomicAdd(&g_numdead, 1);
}

// --------------------- aux top-512 per row (dead mask) ----------------------
__global__ void k_aux() {
    int r = blockIdx.x, t = threadIdx.x;
    const float* __restrict__ row = g_acts + (size_t)r*DICTN;
    __shared__ unsigned int hist[256];
    __shared__ unsigned int sT;
    __shared__ int sRem, sCnt, sTc;
    __shared__ int tiebuf[256];

    if (t == 0) { sT = 0u; sRem = K2; }
    __syncthreads();
    for (int pass = 0; pass < 4; ++pass) {
        int shift = 24 - 8*pass;
        hist[t] = 0u; __syncthreads();
        unsigned int pref = sT;
        for (int j = t; j < DICTN; j += 256) {
            unsigned int k = g_dead[j] ? __float_as_uint(row[j]) : 0u;
            bool ok = (pass == 0) || (((k ^ pref) >> (shift + 8)) == 0u);
            if (ok) atomicAdd(&hist[(k >> shift) & 255u], 1u);
        }
        __syncthreads();
        if (t == 0) {
            int rem = sRem, b = 255;
            for (;;) {
                int cn = (int)hist[b];
                if (cn >= rem || b == 0) break;
                rem -= cn; --b;
            }
            sRem = rem;
            sT = pref | ((unsigned int)b << shift);
        }
        __syncthreads();
    }
    unsigned int T = sT;
    int need = sRem;
    if (t == 0) { sCnt = 0; sTc = 0; }
    __syncthreads();
    for (int j = t; j < DICTN; j += 256) {
        float v = row[j];
        unsigned int k = g_dead[j] ? __float_as_uint(v) : 0u;
        if (k > T) {
            int p = atomicAdd(&sCnt, 1);
            g_vaux[(size_t)r*K2 + p] = v;
            g_iaux[(size_t)r*K2 + p] = j;
        } else if (T != 0u && k == T) {
            int p = atomicAdd(&sTc, 1);
            if (p < 256) tiebuf[p] = j;
        }
    }
    __syncthreads();
    if (t == 0) {
        int G = sCnt;
        int tc = sTc < 256 ? sTc : 256;
        int taken = 0;
        if (T != 0u) {
            int want = need < tc ? need : tc;
            for (int q = 0; q < want; ++q) {
                int best = 0x7fffffff, bi = -1;
                for (int u = 0; u < tc; ++u) {
                    int id = tiebuf[u];
                    if (id >= 0 && id < best) { best = id; bi = u; }
                }
                tiebuf[bi] = -1;
                g_vaux[(size_t)r*K2 + G + q] = __uint_as_float(T);
                g_iaux[(size_t)r*K2 + G + q] = best;
            }
            taken = want;
        }
        g_cntaux[r] = G + taken;
    }
}

// ---------------------- zero + scatter acts_sparse --------------------------
__global__ void k_zero(float* __restrict__ p) {
    size_t i  = (size_t)blockIdx.x*blockDim.x + threadIdx.x;
    size_t n4 = (size_t)NB*DICTN/4;
    float4 z = {0.f, 0.f, 0.f, 0.f};
    for (size_t j = i; j < n4; j += (size_t)gridDim.x*blockDim.x)
        ((float4*)p)[j] = z;
}
__global__ void k_scatter(float* __restrict__ p) {
    int i = blockIdx.x*256 + threadIdx.x;
    if (i >= NB*K1) return;
    int r = i / K1;
    int id = g_i32[i];
    if (id >= 0) p[(size_t)r*DICTN + id] = g_v32[i];
}

// ------------------------ decode + per-row losses ---------------------------
__global__ void k_decode(const float* __restrict__ Wd, const float* __restrict__ bdec,
                         float* __restrict__ outy) {
    int r = blockIdx.x, t = threadIdx.x;
    __shared__ float sv[K1]; __shared__ int si[K1];
    __shared__ float av[K2]; __shared__ int ai[K2];
    __shared__ float red[256];
    if (t < K1) { sv[t] = g_v32[r*K1 + t]; si[t] = g_i32[r*K1 + t]; }
    int cnt = g_cntaux[r];
    for (int q = t; q < cnt; q += 256) {
        av[q] = g_vaux[(size_t)r*K2 + q];
        ai[q] = g_iaux[(size_t)r*K2 + q];
    }
    __syncthreads();
    float ymean = g_ymean[r], ystd = g_ystd[r];
    float l2p = 0.f, auxp = 0.f;
    for (int d = t; d < DOUT; d += 256) {
        float yp = bdec[d];
#pragma unroll
        for (int q = 0; q < K1; q++) {
            int id = si[q];
            if (id >= 0) yp += sv[q] * Wd[(size_t)id*DOUT + d];
        }
        float ynv = g_yn[r*DOUT + d];
        outy[(size_t)r*DOUT + d] = yp*ystd + ymean;
        float e = yp - ynv;
        l2p += e*e;
        float ya0 = 0.f, ya1 = 0.f;
        int q = 0;
        for (; q + 1 < cnt; q += 2) {
            ya0 += av[q]   * Wd[(size_t)ai[q]  *DOUT + d];
            ya1 += av[q+1] * Wd[(size_t)ai[q+1]*DOUT + d];
        }
        if (q < cnt) ya0 += av[q] * Wd[(size_t)ai[q]*DOUT + d];
        float ea = (ya0 + ya1) - (ynv - yp);
        auxp += ea*ea;
    }
    red[t] = l2p; __syncthreads();
    for (int o = 128; o > 0; o >>= 1) { if (t < o) red[t] += red[t+o]; __syncthreads(); }
    if (t == 0) g_rowl2[r] = red[0];
    __syncthreads();
    red[t] = auxp; __syncthreads();
    for (int o = 128; o > 0; o >>= 1) { if (t < o) red[t] += red[t+o]; __syncthreads(); }
    if (t == 0) g_rowaux[r] = red[0];
}

// ------------------------------ finalize -------------------------------------
__global__ void k_final(float* __restrict__ outsc) {
    int t = threadIdx.x;
    __shared__ float red[256];
    __shared__ float res[4];
    const float* arrs[4] = { g_rowl2, g_rowaux, g_rowl1, g_rowl0 };
    for (int a = 0; a < 4; a++) {
        float s = 0.f;
        for (int j = t; j < NB; j += 256) s += arrs[a][j];
        red[t] = s; __syncthreads();
        for (int o = 128; o > 0; o >>= 1) { if (t < o) red[t] += red[t+o]; __syncthreads(); }
        if (t == 0) res[a] = red[0];
        __syncthreads();
    }
    if (t == 0) {
        float l2   = res[0] / (float)(NB*DOUT);
        float auxm = res[1] / (float)(NB*DOUT);
        float l1n  = res[2] / (float)NB;
        float l0   = res[3] / (float)NB;
        float l1l  = 0.001f * l1n;
        float aux  = g_deadany ? 0.03125f * auxm : 0.f;
        outsc[0] = l2 + l1l + aux;   // loss
        outsc[1] = l2;               // l2_loss
        outsc[2] = l1l;              // l1_loss
        outsc[3] = l0;               // l0_norm
        outsc[4] = l1n;              // l1_norm
        outsc[5] = aux;              // aux_loss
        outsc[6] = (float)g_numdead; // num_dead_features
    }
}

// ------------------------------- launcher ------------------------------------
extern "C" void kernel_launch(void* const* d_in, const int* in_sizes, int n_in,
                              void* d_out, int out_size) {
    (void)in_sizes; (void)n_in; (void)out_size;
    const float* x  = (const float*)d_in[0];   // x_in
    const float* y  = (const float*)d_in[1];   // y_target
    const float* nb = (const float*)d_in[2];   // num_batches_not_active
    const float* We = (const float*)d_in[3];   // W_enc [768, 24576]
    const float* Wd = (const float*)d_in[4];   // W_dec [24576, 768]
    const float* bd = (const float*)d_in[5];   // b_dec [768]
    float* out = (float*)d_out;

    k_init   <<<DICTN/256, 256>>>();
    k_norm   <<<NB, 256>>>(x, y, bd);
    k_gemm   <<<dim3(DICTN/BN, NB/BM), 256>>>(We);
    k_top32  <<<NB, 256>>>();
    k_dead   <<<DICTN/256, 256>>>(nb);
    k_aux    <<<NB, 256>>>();
    k_zero   <<<4096, 256>>>(out + S_OFS);
    k_scatter<<<(NB*K1)/256, 256>>>(out + S_OFS);
    k_decode <<<NB, 256>>>(Wd, bd, out);
    k_final  <<<1, 256>>>(out + SC_OFS);
}

// round 4
// speedup vs baseline: 1.1700x; 1.1694x over previous
#include <cuda_runtime.h>
#include <cuda_bf16.h>
#include <cstdint>

#define NB    2048
#define DIN   768
#define DOUT  768
#define DICTN 24576
#define K1    32
#define K2    512

#define S_OFS  (NB*DOUT)
#define SC_OFS (S_OFS + NB*DICTN)

// ------------------------- scratch (device globals) -------------------------
__device__ float g_acts[(size_t)NB*DICTN];          // approx acts (bf16x3 MMA), relu'd
__device__ float g_xe[NB*DIN];                      // exact fp32 x_enc
__device__ __nv_bfloat16 g_ahi[NB*DIN];
__device__ __nv_bfloat16 g_alo[NB*DIN];
__device__ float g_wt [(size_t)DICTN*DIN];          // W_enc transposed fp32 [n][k]
__device__ __nv_bfloat16 g_whi[(size_t)DICTN*DIN];  // transposed bf16 hi
__device__ __nv_bfloat16 g_wlo[(size_t)DICTN*DIN];  // transposed bf16 lo
__device__ float g_yn[NB*DOUT];
__device__ float g_ymean[NB];
__device__ float g_ystd[NB];
__device__ float g_v32[NB*K1];
__device__ int   g_i32[NB*K1];
__device__ float g_rowl1[NB];
__device__ float g_rowl0[NB];
__device__ float g_rowl2[NB];
__device__ float g_rowaux[NB];
__device__ int   g_colact[DICTN];
__device__ unsigned int g_deadmask[DICTN/32];
__device__ int   g_numdead;
__device__ int   g_deadany;
__device__ float g_vaux[(size_t)NB*K2];
__device__ int   g_iaux[(size_t)NB*K2];
__device__ int   g_cntaux[NB];

// --------------------------- helpers -----------------------------------------
__device__ __forceinline__ uint32_t smem_u32(const void* p) {
    uint32_t a;
    asm("{ .reg .u64 t; cvta.to.shared.u64 t, %1; cvt.u32.u64 %0, t; }"
        : "=r"(a) : "l"(p));
    return a;
}
__device__ __forceinline__ void cpa16(uint32_t dst, const void* src) {
    asm volatile("cp.async.ca.shared.global [%0], [%1], 16;"
                 :: "r"(dst), "l"(src) : "memory");
}
__device__ __forceinline__ void ldm4(uint32_t* r, uint32_t addr) {
    asm volatile("ldmatrix.sync.aligned.m8n8.x4.shared.b16 {%0,%1,%2,%3}, [%4];"
                 : "=r"(r[0]), "=r"(r[1]), "=r"(r[2]), "=r"(r[3]) : "r"(addr));
}
__device__ __forceinline__ void mma16816(float* d, const uint32_t* a,
                                         uint32_t b0, uint32_t b1) {
    asm volatile(
        "mma.sync.aligned.m16n8k16.row.col.f32.bf16.bf16.f32 "
        "{%0,%1,%2,%3}, {%4,%5,%6,%7}, {%8,%9}, {%0,%1,%2,%3};"
        : "+f"(d[0]), "+f"(d[1]), "+f"(d[2]), "+f"(d[3])
        : "r"(a[0]), "r"(a[1]), "r"(a[2]), "r"(a[3]), "r"(b0), "r"(b1));
}

// ------------------------------- init ---------------------------------------
__global__ void k_init() {
    int i = blockIdx.x*blockDim.x + threadIdx.x;
    if (i < DICTN) g_colact[i] = 0;
    if (i == 0) { g_numdead = 0; g_deadany = 0; }
}

// --------------------------- row normalization + A split --------------------
__global__ void k_norm(const float* __restrict__ x, const float* __restrict__ y,
                       const float* __restrict__ bdec) {
    int r = blockIdx.x, t = threadIdx.x;
    __shared__ float red[256];

    float x0 = x[r*DIN + t], x1 = x[r*DIN + t + 256], x2 = x[r*DIN + t + 512];
    red[t] = x0 + x1 + x2; __syncthreads();
    for (int o = 128; o > 0; o >>= 1) { if (t < o) red[t] += red[t+o]; __syncthreads(); }
    float m = red[0] * (1.0f/DIN);
    __syncthreads();
    float d0 = x0 - m, d1 = x1 - m, d2 = x2 - m;
    red[t] = d0*d0 + d1*d1 + d2*d2; __syncthreads();
    for (int o = 128; o > 0; o >>= 1) { if (t < o) red[t] += red[t+o]; __syncthreads(); }
    float s = sqrtf(red[0] * (1.0f/(DIN-1)));
    __syncthreads();
    float inv = 1.0f/(s + 1e-5f);
    float e0 = d0*inv - bdec[t];
    float e1 = d1*inv - bdec[t+256];
    float e2 = d2*inv - bdec[t+512];
    g_xe[r*DIN + t]       = e0;
    g_xe[r*DIN + t + 256] = e1;
    g_xe[r*DIN + t + 512] = e2;
    {
        __nv_bfloat16 h0 = __float2bfloat16(e0);
        __nv_bfloat16 h1 = __float2bfloat16(e1);
        __nv_bfloat16 h2 = __float2bfloat16(e2);
        g_ahi[r*DIN + t] = h0; g_ahi[r*DIN + t + 256] = h1; g_ahi[r*DIN + t + 512] = h2;
        g_alo[r*DIN + t]       = __float2bfloat16(e0 - __bfloat162float(h0));
        g_alo[r*DIN + t + 256] = __float2bfloat16(e1 - __bfloat162float(h1));
        g_alo[r*DIN + t + 512] = __float2bfloat16(e2 - __bfloat162float(h2));
    }

    float y0 = y[r*DOUT + t], y1 = y[r*DOUT + t + 256], y2 = y[r*DOUT + t + 512];
    red[t] = y0 + y1 + y2; __syncthreads();
    for (int o = 128; o > 0; o >>= 1) { if (t < o) red[t] += red[t+o]; __syncthreads(); }
    float my = red[0] * (1.0f/DOUT);
    __syncthreads();
    float f0 = y0 - my, f1 = y1 - my, f2 = y2 - my;
    red[t] = f0*f0 + f1*f1 + f2*f2; __syncthreads();
    for (int o = 128; o > 0; o >>= 1) { if (t < o) red[t] += red[t+o]; __syncthreads(); }
    float sy = sqrtf(red[0] * (1.0f/(DOUT-1)));
    __syncthreads();
    float invy = 1.0f/(sy + 1e-5f);
    g_yn[r*DOUT + t]       = f0*invy;
    g_yn[r*DOUT + t + 256] = f1*invy;
    g_yn[r*DOUT + t + 512] = f2*invy;
    if (t == 0) { g_ymean[r] = my; g_ystd[r] = sy; }
}

// ------------------- W_enc transpose + bf16 split ----------------------------
__global__ void k_convB(const float* __restrict__ We) {
    __shared__ float tile[32][33];
    int n0 = blockIdx.x*32, k0 = blockIdx.y*32;
    int tx = threadIdx.x, ty = threadIdx.y;
#pragma unroll
    for (int i = 0; i < 4; i++)
        tile[ty + i*8][tx] = We[(size_t)(k0 + ty + i*8)*DICTN + n0 + tx];
    __syncthreads();
#pragma unroll
    for (int i = 0; i < 4; i++) {
        int n = n0 + ty + i*8, k = k0 + tx;
        float v = tile[tx][ty + i*8];
        g_wt[(size_t)n*DIN + k] = v;
        __nv_bfloat16 h = __float2bfloat16(v);
        g_whi[(size_t)n*DIN + k] = h;
        g_wlo[(size_t)n*DIN + k] = __float2bfloat16(v - __bfloat162float(h));
    }
}

// ------------------------------ HMMA GEMM ------------------------------------
// acts[2048,24576] ~= relu(xe @ W); 128x128 CTA tile, BK=32, bf16x3 split.
#define PITCH    80        /* bytes per 32-bf16 row (16B*5 -> conflict-free ldmatrix) */
#define MATSZ    10240     /* 128 rows * 80 B */
#define OF_AL    10240
#define OF_BH    20480
#define OF_BL    30720
#define STAGE_SZ 40960
#define MMA_SMEM (2*STAGE_SZ)
#define NSTAGE   (DIN/32)  /* 24 */

__global__ void __launch_bounds__(256) k_mma() {
    extern __shared__ char sm[];
    uint32_t smb = smem_u32(sm);
    int t = threadIdx.x, lid = t & 31, wid = t >> 5;
    int m0 = blockIdx.x * 128, n0 = blockIdx.y * 128;
    int warpM = wid & 1, warpN = wid >> 1;

    float acc[4][4][4];
#pragma unroll
    for (int i = 0; i < 4; i++)
#pragma unroll
        for (int j = 0; j < 4; j++)
#pragma unroll
            for (int q = 0; q < 4; q++) acc[i][j][q] = 0.f;

    // per-stage async copy: 4 matrices x 512 16B-chunks, 8 per thread
    auto issue = [&](int s) {
        int k0 = s * 32;
        uint32_t sb = smb + (s & 1) * STAGE_SZ;
#pragma unroll
        for (int c = t; c < 512; c += 256) {
            int row = c >> 2, ch = c & 3;
            uint32_t d = sb + row*PITCH + ch*16;
            const __nv_bfloat16* a1 = g_ahi + (size_t)(m0+row)*DIN + k0 + ch*8;
            const __nv_bfloat16* a2 = g_alo + (size_t)(m0+row)*DIN + k0 + ch*8;
            const __nv_bfloat16* b1 = g_whi + (size_t)(n0+row)*DIN + k0 + ch*8;
            const __nv_bfloat16* b2 = g_wlo + (size_t)(n0+row)*DIN + k0 + ch*8;
            cpa16(d,         a1);
            cpa16(d + OF_AL, a2);
            cpa16(d + OF_BH, b1);
            cpa16(d + OF_BL, b2);
        }
        asm volatile("cp.async.commit_group;" ::: "memory");
    };

    // ldmatrix lane addressing
    int sub = lid >> 3, le = lid & 7;
    uint32_t aAddr = smb + (uint32_t)(warpM*64 + (sub&1)*8 + le)*PITCH + (sub>>1)*16;
    uint32_t bAddr = smb + OF_BH + (uint32_t)(warpN*32 + (sub>>1)*8 + le)*PITCH + (sub&1)*16;

    issue(0);
    for (int s = 0; s < NSTAGE; ++s) {
        if (s + 1 < NSTAGE) {
            issue(s + 1);
            asm volatile("cp.async.wait_group 1;" ::: "memory");
        } else {
            asm volatile("cp.async.wait_group 0;" ::: "memory");
        }
        __syncthreads();
        uint32_t st = (s & 1) * STAGE_SZ;
#pragma unroll
        for (int kk = 0; kk < 2; ++kk) {
            uint32_t ka = st + kk*32;
            uint32_t ah[4][4], al[4][4], bh[2][4], bl[2][4];
#pragma unroll
            for (int mt = 0; mt < 4; ++mt) {
                ldm4(ah[mt], aAddr + ka + mt*(16*PITCH));
                ldm4(al[mt], aAddr + ka + mt*(16*PITCH) + OF_AL);
            }
#pragma unroll
            for (int bt = 0; bt < 2; ++bt) {
                ldm4(bh[bt], bAddr + ka + bt*(16*PITCH));
                ldm4(bl[bt], bAddr + ka + bt*(16*PITCH) + (OF_BL - OF_BH));
            }
#pragma unroll
            for (int mt = 0; mt < 4; ++mt) {
#pragma unroll
                for (int nt = 0; nt < 4; ++nt) {
                    int bt = nt >> 1, pr = (nt & 1) * 2;
                    mma16816(acc[mt][nt], ah[mt], bh[bt][pr], bh[bt][pr+1]);
                    mma16816(acc[mt][nt], ah[mt], bl[bt][pr], bl[bt][pr+1]);
                    mma16816(acc[mt][nt], al[mt], bh[bt][pr], bh[bt][pr+1]);
                }
            }
        }
        __syncthreads();
    }

    // epilogue: relu + store
    int rbase = m0 + warpM*64 + (lid >> 2);
    int cbase = n0 + warpN*32 + (lid & 3)*2;
#pragma unroll
    for (int mt = 0; mt < 4; ++mt) {
#pragma unroll
        for (int nt = 0; nt < 4; ++nt) {
            int gr = rbase + mt*16, gc = cbase + nt*8;
            float2 v0, v1;
            v0.x = fmaxf(acc[mt][nt][0], 0.f);
            v0.y = fmaxf(acc[mt][nt][1], 0.f);
            v1.x = fmaxf(acc[mt][nt][2], 0.f);
            v1.y = fmaxf(acc[mt][nt][3], 0.f);
            *(float2*)(g_acts + (size_t)gr*DICTN + gc)       = v0;
            *(float2*)(g_acts + (size_t)(gr+8)*DICTN + gc)   = v1;
        }
    }
}

// ------------------ top-32: screen (approx) + exact recompute ----------------
#define CCAP 192
__global__ void k_screen32() {
    int r = blockIdx.x, t = threadIdx.x;
    const float* __restrict__ row = g_acts + (size_t)r*DICTN;
    __shared__ uint32_t hist[4096];
    __shared__ int sB, sNc;
    __shared__ int   cidx[CCAP];
    __shared__ float cval[CCAP];
    __shared__ float xs[DIN];
    __shared__ float selv[K1];
    __shared__ int   seli[K1];

    for (int i = t; i < 4096; i += 256) hist[i] = 0u;
    for (int i = t; i < DIN;  i += 256) xs[i] = g_xe[r*DIN + i];
    if (t < K1) { selv[t] = 0.f; seli[t] = -1; }
    if (t == 0) sNc = 0;
    __syncthreads();
    for (int j = t; j < DICTN; j += 256) {
        float v = row[j];
        if (v > 0.f) {
            int b = (int)(v * 256.0f);
            if (b > 4095) b = 4095;
            atomicAdd(&hist[b], 1u);
        }
    }
    __syncthreads();
    if (t == 0) {
        int cum = 0, b = 4095;
        for (; b > 0; --b) { cum += (int)hist[b]; if (cum >= K1) break; }
        sB = b;
    }
    __syncthreads();
    float thr = (float)sB * (1.0f/256.0f) - 0.03f;   // margin >> 2*mma-err
    for (int j = t; j < DICTN; j += 256) {
        float v = row[j];
        if (v > 0.f && v >= thr) {
            int p = atomicAdd(&sNc, 1);
            if (p < CCAP) cidx[p] = j;
        }
    }
    __syncthreads();
    int nc = sNc < CCAP ? sNc : CCAP;
    // exact fp32 recompute per candidate (warp-dot)
    for (int c = (t >> 5); c < nc; c += 8) {
        const float* wr = g_wt + (size_t)cidx[c]*DIN;
        float s = 0.f;
        for (int k = (t & 31); k < DIN; k += 32) s = fmaf(xs[k], wr[k], s);
#pragma unroll
        for (int o = 16; o > 0; o >>= 1) s += __shfl_xor_sync(0xffffffffu, s, o);
        if ((t & 31) == 0) cval[c] = s;
    }
    __syncthreads();
    if (t < nc) {
        float v = fmaxf(cval[t], 0.f);
        int idx = cidx[t];
        int rank = 0;
        for (int u = 0; u < nc; ++u) {
            float vu = fmaxf(cval[u], 0.f);
            if (vu > v || (vu == v && cidx[u] < idx)) rank++;
        }
        if (rank < K1) { selv[rank] = v; seli[rank] = idx; }
    }
    __syncthreads();
    if (t < K1) {
        g_v32[r*K1 + t] = selv[t];
        g_i32[r*K1 + t] = seli[t];
        if (selv[t] > 0.f && seli[t] >= 0) g_colact[seli[t]] = 1;
    }
    if (t == 0) {
        float l1 = 0.f, l0 = 0.f;
        for (int q = 0; q < K1; ++q)
            if (selv[q] > 0.f) { l1 += selv[q]; l0 += 1.f; }
        g_rowl1[r] = l1; g_rowl0[r] = l0;
    }
}

// ----------------------- dead-feature bookkeeping ---------------------------
__global__ void k_dead(const float* __restrict__ nb) {
    int c = blockIdx.x*256 + threadIdx.x;
    float nbn = g_colact[c] ? 0.f : nb[c] + 1.f;
    int dead = (nbn >= 100.f) ? 1 : 0;
    unsigned m = __ballot_sync(0xffffffffu, dead);
    if ((threadIdx.x & 31) == 0) g_deadmask[c >> 5] = m;
    if (dead) atomicOr(&g_deadany, 1);
    if (nbn > 100.f) atomicAdd(&g_numdead, 1);
}

// --------------------- aux top-512 per row (dead mask) ----------------------
#define ACAP 1024
__global__ void k_aux() {
    int r = blockIdx.x, t = threadIdx.x;
    const float* __restrict__ row = g_acts + (size_t)r*DICTN;
    __shared__ uint32_t hist[4096];
    __shared__ unsigned int dm[DICTN/32];
    __shared__ int sB, sNc;
    __shared__ float avv[ACAP];
    __shared__ int   aid[ACAP];

    for (int i = t; i < 4096; i += 256) hist[i] = 0u;
    for (int i = t; i < DICTN/32; i += 256) dm[i] = g_deadmask[i];
    if (t == 0) sNc = 0;
    __syncthreads();
    for (int j = t; j < DICTN; j += 256) {
        float v = row[j];
        if (v > 0.f && ((dm[j>>5] >> (j & 31)) & 1u)) {
            int b = (int)(v * 256.0f);
            if (b > 4095) b = 4095;
            atomicAdd(&hist[b], 1u);
        }
    }
    __syncthreads();
    if (t == 0) {
        int cum = 0, b = 4095;
        for (; b > 0; --b) { cum += (int)hist[b]; if (cum >= K2) break; }
        sB = b;
    }
    __syncthreads();
    float thr = (float)sB * (1.0f/256.0f);
    for (int j = t; j < DICTN; j += 256) {
        float v = row[j];
        if (v > 0.f && v >= thr && ((dm[j>>5] >> (j & 31)) & 1u)) {
            int p = atomicAdd(&sNc, 1);
            if (p < ACAP) { avv[p] = v; aid[p] = j; }
        }
    }
    __syncthreads();
    int nc = sNc < ACAP ? sNc : ACAP;
    for (int c = t; c < nc; c += 256) {
        float v = avv[c]; int idx = aid[c];
        int rank = 0;
        for (int u = 0; u < nc; ++u) {
            float vu = avv[u];
            if (vu > v || (vu == v && aid[u] < idx)) rank++;
        }
        if (rank < K2) {
            g_vaux[(size_t)r*K2 + rank] = v;
            g_iaux[(size_t)r*K2 + rank] = idx;
        }
    }
    if (t == 0) g_cntaux[r] = nc < K2 ? nc : K2;
}

// ---------------------- zero + scatter acts_sparse --------------------------
__global__ void k_zero(float* __restrict__ p) {
    size_t i  = (size_t)blockIdx.x*blockDim.x + threadIdx.x;
    size_t n4 = (size_t)NB*DICTN/4;
    float4 z = {0.f, 0.f, 0.f, 0.f};
    for (size_t j = i; j < n4; j += (size_t)gridDim.x*blockDim.x)
        ((float4*)p)[j] = z;
}
__global__ void k_scatter(float* __restrict__ p) {
    int i = blockIdx.x*256 + threadIdx.x;
    if (i >= NB*K1) return;
    int r = i / K1;
    int id = g_i32[i];
    if (id >= 0) p[(size_t)r*DICTN + id] = g_v32[i];
}

// ------------------------ decode + per-row losses ---------------------------
__global__ void k_decode(const float* __restrict__ Wd, const float* __restrict__ bdec,
                         float* __restrict__ outy) {
    int r = blockIdx.x, t = threadIdx.x;
    __shared__ float sv[K1]; __shared__ int si[K1];
    __shared__ float av[K2]; __shared__ int ai[K2];
    __shared__ float red[256];
    if (t < K1) { sv[t] = g_v32[r*K1 + t]; si[t] = g_i32[r*K1 + t]; }
    int cnt = g_cntaux[r];
    for (int q = t; q < cnt; q += 256) {
        av[q] = g_vaux[(size_t)r*K2 + q];
        ai[q] = g_iaux[(size_t)r*K2 + q];
    }
    __syncthreads();
    float ymean = g_ymean[r], ystd = g_ystd[r];
    float l2p = 0.f, auxp = 0.f;
    for (int d = t; d < DOUT; d += 256) {
        float yp = bdec[d];
#pragma unroll
        for (int q = 0; q < K1; q++) {
            int id = si[q];
            if (id >= 0) yp += sv[q] * Wd[(size_t)id*DOUT + d];
        }
        float ynv = g_yn[r*DOUT + d];
        outy[(size_t)r*DOUT + d] = yp*ystd + ymean;
        float e = yp - ynv;
        l2p += e*e;
        float ya0 = 0.f, ya1 = 0.f;
        int q = 0;
        for (; q + 1 < cnt; q += 2) {
            ya0 += av[q]   * Wd[(size_t)ai[q]  *DOUT + d];
            ya1 += av[q+1] * Wd[(size_t)ai[q+1]*DOUT + d];
        }
        if (q < cnt) ya0 += av[q] * Wd[(size_t)ai[q]*DOUT + d];
        float ea = (ya0 + ya1) - (ynv - yp);
        auxp += ea*ea;
    }
    red[t] = l2p; __syncthreads();
    for (int o = 128; o > 0; o >>= 1) { if (t < o) red[t] += red[t+o]; __syncthreads(); }
    if (t == 0) g_rowl2[r] = red[0];
    __syncthreads();
    red[t] = auxp; __syncthreads();
    for (int o = 128; o > 0; o >>= 1) { if (t < o) red[t] += red[t+o]; __syncthreads(); }
    if (t == 0) g_rowaux[r] = red[0];
}

// ------------------------------ finalize -------------------------------------
__global__ void k_final(float* __restrict__ outsc) {
    int t = threadIdx.x;
    __shared__ float red[256];
    __shared__ float res[4];
    const float* arrs[4] = { g_rowl2, g_rowaux, g_rowl1, g_rowl0 };
    for (int a = 0; a < 4; a++) {
        float s = 0.f;
        for (int j = t; j < NB; j += 256) s += arrs[a][j];
        red[t] = s; __syncthreads();
        for (int o = 128; o > 0; o >>= 1) { if (t < o) red[t] += red[t+o]; __syncthreads(); }
        if (t == 0) res[a] = red[0];
        __syncthreads();
    }
    if (t == 0) {
        float l2   = res[0] / (float)(NB*DOUT);
        float auxm = res[1] / (float)(NB*DOUT);
        float l1n  = res[2] / (float)NB;
        float l0   = res[3] / (float)NB;
        float l1l  = 0.001f * l1n;
        float aux  = g_deadany ? 0.03125f * auxm : 0.f;
        outsc[0] = l2 + l1l + aux;
        outsc[1] = l2;
        outsc[2] = l1l;
        outsc[3] = l0;
        outsc[4] = l1n;
        outsc[5] = aux;
        outsc[6] = (float)g_numdead;
    }
}

// ------------------------------- launcher ------------------------------------
extern "C" void kernel_launch(void* const* d_in, const int* in_sizes, int n_in,
                              void* d_out, int out_size) {
    (void)in_sizes; (void)n_in; (void)out_size;
    const float* x  = (const float*)d_in[0];
    const float* y  = (const float*)d_in[1];
    const float* nb = (const float*)d_in[2];
    const float* We = (const float*)d_in[3];
    const float* Wd = (const float*)d_in[4];
    const float* bd = (const float*)d_in[5];
    float* out = (float*)d_out;

    cudaFuncSetAttribute(k_mma, cudaFuncAttributeMaxDynamicSharedMemorySize, MMA_SMEM);

    k_init    <<<DICTN/256, 256>>>();
    k_norm    <<<NB, 256>>>(x, y, bd);
    k_convB   <<<dim3(DICTN/32, DIN/32), dim3(32, 8)>>>(We);
    k_mma     <<<dim3(NB/128, DICTN/128), 256, MMA_SMEM>>>();
    k_screen32<<<NB, 256>>>();
    k_dead    <<<DICTN/256, 256>>>(nb);
    k_aux     <<<NB, 256>>>();
    k_zero    <<<4096, 256>>>(out + S_OFS);
    k_scatter <<<(NB*K1)/256, 256>>>(out + S_OFS);
    k_decode  <<<NB, 256>>>(Wd, bd, out);
    k_final   <<<1, 256>>>(out + SC_OFS);
}

// round 5
// speedup vs baseline: 1.3563x; 1.1592x over previous
#include <cuda_runtime.h>
#include <cuda_bf16.h>
#include <cstdint>

#define NB    2048
#define DIN   768
#define DOUT  768
#define DICTN 24576
#define K1    32
#define K2    512

#define S_OFS  (NB*DOUT)
#define SC_OFS (S_OFS + NB*DICTN)

// ------------------------- scratch (device globals) -------------------------
__device__ __nv_bfloat16 g_actsb[(size_t)NB*DICTN];  // approx acts, relu'd, bf16
__device__ float g_xe[NB*DIN];                       // exact fp32 x_enc
__device__ __nv_bfloat16 g_ahi[NB*DIN];
__device__ float g_wt [(size_t)DICTN*DIN];           // W_enc^T fp32 [n][k]
__device__ __nv_bfloat16 g_whi[(size_t)DICTN*DIN];   // W_enc^T bf16
__device__ __nv_bfloat16 g_wdh[(size_t)DICTN*DOUT];  // W_dec bf16
__device__ float g_yn[NB*DOUT];
__device__ float g_ymean[NB];
__device__ float g_ystd[NB];
__device__ float g_v32[NB*K1];
__device__ int   g_i32[NB*K1];
__device__ float g_rowl1[NB];
__device__ float g_rowl0[NB];
__device__ float g_rowl2[NB];
__device__ float g_rowaux[NB];
__device__ int   g_colact[DICTN];
__device__ unsigned int g_deadmask[DICTN/32];
__device__ int   g_numdead;
__device__ int   g_deadany;
__device__ float g_vaux[(size_t)NB*K2];
__device__ int   g_iaux[(size_t)NB*K2];
__device__ int   g_cntaux[NB];

// --------------------------- helpers -----------------------------------------
__device__ __forceinline__ uint32_t smem_u32(const void* p) {
    uint32_t a;
    asm("{ .reg .u64 t; cvta.to.shared.u64 t, %1; cvt.u32.u64 %0, t; }"
        : "=r"(a) : "l"(p));
    return a;
}
__device__ __forceinline__ void cpa16(uint32_t dst, const void* src) {
    asm volatile("cp.async.ca.shared.global [%0], [%1], 16;"
                 :: "r"(dst), "l"(src) : "memory");
}
__device__ __forceinline__ void ldm4(uint32_t* r, uint32_t addr) {
    asm volatile("ldmatrix.sync.aligned.m8n8.x4.shared.b16 {%0,%1,%2,%3}, [%4];"
                 : "=r"(r[0]), "=r"(r[1]), "=r"(r[2]), "=r"(r[3]) : "r"(addr));
}
__device__ __forceinline__ void mma16816(float* d, const uint32_t* a,
                                         uint32_t b0, uint32_t b1) {
    asm volatile(
        "mma.sync.aligned.m16n8k16.row.col.f32.bf16.bf16.f32 "
        "{%0,%1,%2,%3}, {%4,%5,%6,%7}, {%8,%9}, {%0,%1,%2,%3};"
        : "+f"(d[0]), "+f"(d[1]), "+f"(d[2]), "+f"(d[3])
        : "r"(a[0]), "r"(a[1]), "r"(a[2]), "r"(a[3]), "r"(b0), "r"(b1));
}

// ------------------------------- init ---------------------------------------
__global__ void k_init() {
    int i = blockIdx.x*blockDim.x + threadIdx.x;
    if (i < DICTN) g_colact[i] = 0;
    if (i == 0) { g_numdead = 0; g_deadany = 0; }
}

// --------------------------- row normalization ------------------------------
__global__ void k_norm(const float* __restrict__ x, const float* __restrict__ y,
                       const float* __restrict__ bdec) {
    int r = blockIdx.x, t = threadIdx.x;
    __shared__ float red[256];

    float x0 = x[r*DIN + t], x1 = x[r*DIN + t + 256], x2 = x[r*DIN + t + 512];
    red[t] = x0 + x1 + x2; __syncthreads();
    for (int o = 128; o > 0; o >>= 1) { if (t < o) red[t] += red[t+o]; __syncthreads(); }
    float m = red[0] * (1.0f/DIN);
    __syncthreads();
    float d0 = x0 - m, d1 = x1 - m, d2 = x2 - m;
    red[t] = d0*d0 + d1*d1 + d2*d2; __syncthreads();
    for (int o = 128; o > 0; o >>= 1) { if (t < o) red[t] += red[t+o]; __syncthreads(); }
    float s = sqrtf(red[0] * (1.0f/(DIN-1)));
    __syncthreads();
    float inv = 1.0f/(s + 1e-5f);
    float e0 = d0*inv - bdec[t];
    float e1 = d1*inv - bdec[t+256];
    float e2 = d2*inv - bdec[t+512];
    g_xe[r*DIN + t]       = e0;
    g_xe[r*DIN + t + 256] = e1;
    g_xe[r*DIN + t + 512] = e2;
    g_ahi[r*DIN + t]       = __float2bfloat16(e0);
    g_ahi[r*DIN + t + 256] = __float2bfloat16(e1);
    g_ahi[r*DIN + t + 512] = __float2bfloat16(e2);

    float y0 = y[r*DOUT + t], y1 = y[r*DOUT + t + 256], y2 = y[r*DOUT + t + 512];
    red[t] = y0 + y1 + y2; __syncthreads();
    for (int o = 128; o > 0; o >>= 1) { if (t < o) red[t] += red[t+o]; __syncthreads(); }
    float my = red[0] * (1.0f/DOUT);
    __syncthreads();
    float f0 = y0 - my, f1 = y1 - my, f2 = y2 - my;
    red[t] = f0*f0 + f1*f1 + f2*f2; __syncthreads();
    for (int o = 128; o > 0; o >>= 1) { if (t < o) red[t] += red[t+o]; __syncthreads(); }
    float sy = sqrtf(red[0] * (1.0f/(DOUT-1)));
    __syncthreads();
    float invy = 1.0f/(sy + 1e-5f);
    g_yn[r*DOUT + t]       = f0*invy;
    g_yn[r*DOUT + t + 256] = f1*invy;
    g_yn[r*DOUT + t + 512] = f2*invy;
    if (t == 0) { g_ymean[r] = my; g_ystd[r] = sy; }
}

// ------------------- W_enc transpose (fp32 + bf16) ---------------------------
__global__ void k_convB(const float* __restrict__ We) {
    __shared__ float tile[32][33];
    int n0 = blockIdx.x*32, k0 = blockIdx.y*32;
    int tx = threadIdx.x, ty = threadIdx.y;
#pragma unroll
    for (int i = 0; i < 4; i++)
        tile[ty + i*8][tx] = We[(size_t)(k0 + ty + i*8)*DICTN + n0 + tx];
    __syncthreads();
#pragma unroll
    for (int i = 0; i < 4; i++) {
        int n = n0 + ty + i*8, k = k0 + tx;
        float v = tile[tx][ty + i*8];
        g_wt[(size_t)n*DIN + k] = v;
        g_whi[(size_t)n*DIN + k] = __float2bfloat16(v);
    }
}

// ------------------- W_dec bf16 copy -----------------------------------------
__global__ void k_convD(const float* __restrict__ Wd) {
    size_t i = (size_t)blockIdx.x*256 + threadIdx.x;     // one float4 each
    float4 v = ((const float4*)Wd)[i];
    __nv_bfloat162 p0 = __floats2bfloat162_rn(v.x, v.y);
    __nv_bfloat162 p1 = __floats2bfloat162_rn(v.z, v.w);
    ((__nv_bfloat162*)g_wdh)[i*2]   = p0;
    ((__nv_bfloat162*)g_wdh)[i*2+1] = p1;
}

// ------------------------------ HMMA GEMM ------------------------------------
// actsb[2048,24576] ~= relu(xe @ W), single bf16 hi*hi MMA, 128x128, BK=32, 4-stage.
#define PITCH    80
#define OF_B     10240
#define STG      20480
#define MMA_SMEM (4*STG)
#define NS       (DIN/32)   /* 24 */

__global__ void __launch_bounds__(256, 2) k_mma() {
    extern __shared__ char sm[];
    uint32_t smb = smem_u32(sm);
    int t = threadIdx.x, lid = t & 31, wid = t >> 5;
    int m0 = blockIdx.x * 128, n0 = blockIdx.y * 128;
    int warpM = wid & 1, warpN = wid >> 1;

    float acc[4][4][4];
#pragma unroll
    for (int i = 0; i < 4; i++)
#pragma unroll
        for (int j = 0; j < 4; j++)
#pragma unroll
            for (int q = 0; q < 4; q++) acc[i][j][q] = 0.f;

    auto issue = [&](int s) {
        int k0 = s * 32;
        uint32_t sb = smb + (s & 3) * STG;
#pragma unroll
        for (int c = t; c < 1024; c += 256) {
            int isB = c >> 9;
            int cc = c & 511;
            int row = cc >> 2, ch = cc & 3;
            uint32_t d = sb + isB*OF_B + row*PITCH + ch*16;
            const __nv_bfloat16* src = isB
                ? g_whi + (size_t)(n0+row)*DIN + k0 + ch*8
                : g_ahi + (size_t)(m0+row)*DIN + k0 + ch*8;
            cpa16(d, src);
        }
        asm volatile("cp.async.commit_group;" ::: "memory");
    };

    int sub = lid >> 3, le = lid & 7;
    uint32_t aAddr = smb + (uint32_t)(warpM*64 + (sub&1)*8 + le)*PITCH + (sub>>1)*16;
    uint32_t bAddr = smb + OF_B + (uint32_t)(warpN*32 + (sub>>1)*8 + le)*PITCH + (sub&1)*16;

    issue(0); issue(1); issue(2);
    for (int s = 0; s < NS; ++s) {
        if (s + 3 < NS) {
            issue(s + 3);
            asm volatile("cp.async.wait_group 3;" ::: "memory");
        } else if (s + 2 < NS) {
            asm volatile("cp.async.wait_group 2;" ::: "memory");
        } else if (s + 1 < NS) {
            asm volatile("cp.async.wait_group 1;" ::: "memory");
        } else {
            asm volatile("cp.async.wait_group 0;" ::: "memory");
        }
        __syncthreads();
        uint32_t st = (s & 3) * STG;
#pragma unroll
        for (int kk = 0; kk < 2; ++kk) {
            uint32_t ka = st + kk*32;
            uint32_t ah[4][4], bh[2][4];
#pragma unroll
            for (int mt = 0; mt < 4; ++mt) ldm4(ah[mt], aAddr + ka + mt*(16*PITCH));
#pragma unroll
            for (int bt = 0; bt < 2; ++bt) ldm4(bh[bt], bAddr + ka + bt*(16*PITCH));
#pragma unroll
            for (int mt = 0; mt < 4; ++mt)
#pragma unroll
                for (int nt = 0; nt < 4; ++nt) {
                    int bt = nt >> 1, pr = (nt & 1) * 2;
                    mma16816(acc[mt][nt], ah[mt], bh[bt][pr], bh[bt][pr+1]);
                }
        }
        __syncthreads();
    }

    int rbase = m0 + warpM*64 + (lid >> 2);
    int cbase = n0 + warpN*32 + (lid & 3)*2;
#pragma unroll
    for (int mt = 0; mt < 4; ++mt)
#pragma unroll
        for (int nt = 0; nt < 4; ++nt) {
            int gr = rbase + mt*16, gc = cbase + nt*8;
            __nv_bfloat162 p0 = __floats2bfloat162_rn(fmaxf(acc[mt][nt][0], 0.f),
                                                      fmaxf(acc[mt][nt][1], 0.f));
            __nv_bfloat162 p1 = __floats2bfloat162_rn(fmaxf(acc[mt][nt][2], 0.f),
                                                      fmaxf(acc[mt][nt][3], 0.f));
            *(__nv_bfloat162*)(g_actsb + (size_t)gr*DICTN + gc)     = p0;
            *(__nv_bfloat162*)(g_actsb + (size_t)(gr+8)*DICTN + gc) = p1;
        }
}

// ------------------ top-32: screen (approx) + exact recompute ----------------
#define CCAP 256
#define SCR_SMEM 71680
__global__ void k_screen32() {
    extern __shared__ char sm[];
    __nv_bfloat16* rowb = (__nv_bfloat16*)sm;            // 49152
    uint32_t* hist = (uint32_t*)(sm + 49152);            // 16384
    float* xs   = (float*)(sm + 65536);                  // 3072
    int*   cidx = (int*)  (sm + 68608);                  // 1024
    float* cval = (float*)(sm + 69632);                  // 1024
    float* selv = (float*)(sm + 70656);                  // 128
    int*   seli = (int*)  (sm + 70784);                  // 128
    __shared__ int csum[256];
    __shared__ int sB, sNc;

    int r = blockIdx.x, t = threadIdx.x;
    const uint4* src = (const uint4*)(g_actsb + (size_t)r*DICTN);
#pragma unroll
    for (int i = 0; i < 12; i++) ((uint4*)rowb)[t + i*256] = src[t + i*256];
    for (int i = t; i < 4096; i += 256) hist[i] = 0u;
    for (int i = t; i < DIN;  i += 256) xs[i] = g_xe[r*DIN + i];
    if (t < K1) { selv[t] = 0.f; seli[t] = -1; }
    if (t == 0) sNc = 0;
    __syncthreads();
#pragma unroll 4
    for (int i = 0; i < 96; i++) {
        float v = __bfloat162float(rowb[t + i*256]);
        if (v > 0.f) {
            int b = (int)(v * 256.0f);
            if (b > 4095) b = 4095;
            atomicAdd(&hist[b], 1u);
        }
    }
    __syncthreads();
    int cs = 0;
#pragma unroll
    for (int u = 0; u < 16; u++) cs += (int)hist[t*16 + u];
    csum[t] = cs; __syncthreads();
    for (int o = 1; o < 256; o <<= 1) {
        int v = (t + o < 256) ? csum[t+o] : 0;
        __syncthreads();
        csum[t] += v;
        __syncthreads();
    }
    if (t == 0) {
        int c = 255;
        while (c > 0 && csum[c] < K1) c--;
        int cum = (c < 255) ? csum[c+1] : 0;
        int b = 0;
        for (int bb = c*16 + 15; bb >= c*16; bb--) {
            cum += (int)hist[bb];
            if (cum >= K1) { b = bb; break; }
        }
        sB = b;
    }
    __syncthreads();
    float thr = (float)sB * (1.0f/256.0f) - 0.06f;   // >> 26 sigma of 1-MMA error
#pragma unroll 4
    for (int i = 0; i < 96; i++) {
        float v = __bfloat162float(rowb[t + i*256]);
        if (v > 0.f && v >= thr) {
            int p = atomicAdd(&sNc, 1);
            if (p < CCAP) cidx[p] = t + i*256;
        }
    }
    __syncthreads();
    int nc = sNc < CCAP ? sNc : CCAP;
    for (int c = (t >> 5); c < nc; c += 8) {      // exact fp32 recompute
        const float* wr = g_wt + (size_t)cidx[c]*DIN;
        float s = 0.f;
        for (int k = (t & 31); k < DIN; k += 32) s = fmaf(xs[k], wr[k], s);
#pragma unroll
        for (int o = 16; o > 0; o >>= 1) s += __shfl_xor_sync(0xffffffffu, s, o);
        if ((t & 31) == 0) cval[c] = s;
    }
    __syncthreads();
    if (t < nc) {
        float v = fmaxf(cval[t], 0.f);
        int idx = cidx[t];
        int rank = 0;
        for (int u = 0; u < nc; ++u) {
            float vu = fmaxf(cval[u], 0.f);
            if (vu > v || (vu == v && cidx[u] < idx)) rank++;
        }
        if (rank < K1) { selv[rank] = v; seli[rank] = idx; }
    }
    __syncthreads();
    if (t < K1) {
        g_v32[r*K1 + t] = selv[t];
        g_i32[r*K1 + t] = seli[t];
        if (selv[t] > 0.f && seli[t] >= 0) g_colact[seli[t]] = 1;
    }
    if (t == 0) {
        float l1 = 0.f, l0 = 0.f;
        for (int q = 0; q < K1; ++q)
            if (selv[q] > 0.f) { l1 += selv[q]; l0 += 1.f; }
        g_rowl1[r] = l1; g_rowl0[r] = l0;
    }
}

// ----------------------- dead-feature bookkeeping ---------------------------
__global__ void k_dead(const float* __restrict__ nb) {
    int c = blockIdx.x*256 + threadIdx.x;
    float nbn = g_colact[c] ? 0.f : nb[c] + 1.f;
    int dead = (nbn >= 100.f) ? 1 : 0;
    unsigned m = __ballot_sync(0xffffffffu, dead);
    if ((threadIdx.x & 31) == 0) g_deadmask[c >> 5] = m;
    if (dead) atomicOr(&g_deadany, 1);
    if (nbn > 100.f) atomicAdd(&g_numdead, 1);
}

// --------------------- aux top-512 per row (dead mask) ----------------------
#define ACAP 1024
#define AUX_SMEM 76800
__global__ void k_aux() {
    extern __shared__ char sm[];
    __nv_bfloat16* rowb = (__nv_bfloat16*)sm;            // 49152
    uint32_t* hist = (uint32_t*)(sm + 49152);            // 16384
    unsigned int* dm = (unsigned int*)(sm + 65536);      // 3072
    float* avv = (float*)(sm + 68608);                   // 4096
    int*   aid = (int*)  (sm + 72704);                   // 4096
    __shared__ int csum[256];
    __shared__ int sB, sNc;

    int r = blockIdx.x, t = threadIdx.x;
    const uint4* src = (const uint4*)(g_actsb + (size_t)r*DICTN);
#pragma unroll
    for (int i = 0; i < 12; i++) ((uint4*)rowb)[t + i*256] = src[t + i*256];
    for (int i = t; i < 4096; i += 256) hist[i] = 0u;
    for (int i = t; i < DICTN/32; i += 256) dm[i] = g_deadmask[i];
    if (t == 0) sNc = 0;
    __syncthreads();
#pragma unroll 4
    for (int i = 0; i < 96; i++) {
        int j = t + i*256;
        float v = __bfloat162float(rowb[j]);
        if (v > 0.f && ((dm[j>>5] >> (j & 31)) & 1u)) {
            int b = (int)(v * 256.0f);
            if (b > 4095) b = 4095;
            atomicAdd(&hist[b], 1u);
        }
    }
    __syncthreads();
    int cs = 0;
#pragma unroll
    for (int u = 0; u < 16; u++) cs += (int)hist[t*16 + u];
    csum[t] = cs; __syncthreads();
    for (int o = 1; o < 256; o <<= 1) {
        int v = (t + o < 256) ? csum[t+o] : 0;
        __syncthreads();
        csum[t] += v;
        __syncthreads();
    }
    if (t == 0) {
        int c = 255;
        while (c > 0 && csum[c] < K2) c--;
        int cum = (c < 255) ? csum[c+1] : 0;
        int b = 0;
        for (int bb = c*16 + 15; bb >= c*16; bb--) {
            cum += (int)hist[bb];
            if (cum >= K2) { b = bb; break; }
        }
        sB = b;
    }
    __syncthreads();
    float thr = (float)sB * (1.0f/256.0f);
#pragma unroll 4
    for (int i = 0; i < 96; i++) {
        int j = t + i*256;
        float v = __bfloat162float(rowb[j]);
        if (v > 0.f && v >= thr && ((dm[j>>5] >> (j & 31)) & 1u)) {
            int p = atomicAdd(&sNc, 1);
            if (p < ACAP) { avv[p] = v; aid[p] = j; }
        }
    }
    __syncthreads();
    int nc = sNc < ACAP ? sNc : ACAP;
    for (int c = t; c < nc; c += 256) {
        float v = avv[c]; int idx = aid[c];
        int rank = 0;
        for (int u = 0; u < nc; ++u) {
            float vu = avv[u];
            if (vu > v || (vu == v && aid[u] < idx)) rank++;
        }
        if (rank < K2) {
            g_vaux[(size_t)r*K2 + rank] = v;
            g_iaux[(size_t)r*K2 + rank] = idx;
        }
    }
    if (t == 0) g_cntaux[r] = nc < K2 ? nc : K2;
}

// ---------------------- zero + scatter acts_sparse --------------------------
__global__ void k_zero(float* __restrict__ p) {
    size_t i  = (size_t)blockIdx.x*blockDim.x + threadIdx.x;
    size_t n4 = (size_t)NB*DICTN/4;
    float4 z = {0.f, 0.f, 0.f, 0.f};
    for (size_t j = i; j < n4; j += (size_t)gridDim.x*blockDim.x)
        ((float4*)p)[j] = z;
}
__global__ void k_scatter(float* __restrict__ p) {
    int i = blockIdx.x*256 + threadIdx.x;
    if (i >= NB*K1) return;
    int r = i / K1;
    int id = g_i32[i];
    if (id >= 0) p[(size_t)r*DICTN + id] = g_v32[i];
}

// ------------------------ decode + per-row losses ---------------------------
__global__ void k_decode(const float* __restrict__ Wd, const float* __restrict__ bdec,
                         float* __restrict__ outy) {
    int r = blockIdx.x, t = threadIdx.x;
    __shared__ float sv[K1]; __shared__ int si[K1];
    __shared__ float av[K2]; __shared__ int ai[K2];
    __shared__ float red[256];
    if (t < K1) { sv[t] = g_v32[r*K1 + t]; si[t] = g_i32[r*K1 + t]; }
    int cnt = g_cntaux[r];
    for (int q = t; q < cnt; q += 256) {
        av[q] = g_vaux[(size_t)r*K2 + q];
        ai[q] = g_iaux[(size_t)r*K2 + q];
    }
    __syncthreads();
    float ymean = g_ymean[r], ystd = g_ystd[r];
    float l2p = 0.f, auxp = 0.f;
    for (int d = t; d < DOUT; d += 256) {
        float yp = bdec[d];
#pragma unroll
        for (int q = 0; q < K1; q++) {
            int id = si[q];
            if (id >= 0) yp += sv[q] * Wd[(size_t)id*DOUT + d];
        }
        float ynv = g_yn[r*DOUT + d];
        outy[(size_t)r*DOUT + d] = yp*ystd + ymean;
        float e = yp - ynv;
        l2p += e*e;
        // aux decode with bf16 weights (feeds aux_loss scalar only)
        float ya0 = 0.f, ya1 = 0.f, ya2 = 0.f, ya3 = 0.f;
        int q = 0;
        for (; q + 3 < cnt; q += 4) {
            ya0 += av[q]   * __bfloat162float(g_wdh[(size_t)ai[q]  *DOUT + d]);
            ya1 += av[q+1] * __bfloat162float(g_wdh[(size_t)ai[q+1]*DOUT + d]);
            ya2 += av[q+2] * __bfloat162float(g_wdh[(size_t)ai[q+2]*DOUT + d]);
            ya3 += av[q+3] * __bfloat162float(g_wdh[(size_t)ai[q+3]*DOUT + d]);
        }
        for (; q < cnt; q++)
            ya0 += av[q] * __bfloat162float(g_wdh[(size_t)ai[q]*DOUT + d]);
        float ea = ((ya0 + ya1) + (ya2 + ya3)) - (ynv - yp);
        auxp += ea*ea;
    }
    red[t] = l2p; __syncthreads();
    for (int o = 128; o > 0; o >>= 1) { if (t < o) red[t] += red[t+o]; __syncthreads(); }
    if (t == 0) g_rowl2[r] = red[0];
    __syncthreads();
    red[t] = auxp; __syncthreads();
    for (int o = 128; o > 0; o >>= 1) { if (t < o) red[t] += red[t+o]; __syncthreads(); }
    if (t == 0) g_rowaux[r] = red[0];
}

// ------------------------------ finalize -------------------------------------
__global__ void k_final(float* __restrict__ outsc) {
    int t = threadIdx.x;
    __shared__ float red[256];
    __shared__ float res[4];
    const float* arrs[4] = { g_rowl2, g_rowaux, g_rowl1, g_rowl0 };
    for (int a = 0; a < 4; a++) {
        float s = 0.f;
        for (int j = t; j < NB; j += 256) s += arrs[a][j];
        red[t] = s; __syncthreads();
        for (int o = 128; o > 0; o >>= 1) { if (t < o) red[t] += red[t+o]; __syncthreads(); }
        if (t == 0) res[a] = red[0];
        __syncthreads();
    }
    if (t == 0) {
        float l2   = res[0] / (float)(NB*DOUT);
        float auxm = res[1] / (float)(NB*DOUT);
        float l1n  = res[2] / (float)NB;
        float l0   = res[3] / (float)NB;
        float l1l  = 0.001f * l1n;
        float aux  = g_deadany ? 0.03125f * auxm : 0.f;
        outsc[0] = l2 + l1l + aux;
        outsc[1] = l2;
        outsc[2] = l1l;
        outsc[3] = l0;
        outsc[4] = l1n;
        outsc[5] = aux;
        outsc[6] = (float)g_numdead;
    }
}

// ------------------------------- launcher ------------------------------------
extern "C" void kernel_launch(void* const* d_in, const int* in_sizes, int n_in,
                              void* d_out, int out_size) {
    (void)in_sizes; (void)n_in; (void)out_size;
    const float* x  = (const float*)d_in[0];
    const float* y  = (const float*)d_in[1];
    const float* nb = (const float*)d_in[2];
    const float* We = (const float*)d_in[3];
    const float* Wd = (const float*)d_in[4];
    const float* bd = (const float*)d_in[5];
    float* out = (float*)d_out;

    cudaFuncSetAttribute(k_mma, cudaFuncAttributeMaxDynamicSharedMemorySize, MMA_SMEM);
    cudaFuncSetAttribute(k_screen32, cudaFuncAttributeMaxDynamicSharedMemorySize, SCR_SMEM);
    cudaFuncSetAttribute(k_aux, cudaFuncAttributeMaxDynamicSharedMemorySize, AUX_SMEM);

    k_init    <<<DICTN/256, 256>>>();
    k_norm    <<<NB, 256>>>(x, y, bd);
    k_convB   <<<dim3(DICTN/32, DIN/32), dim3(32, 8)>>>(We);
    k_convD   <<<(DICTN*DOUT/4)/256, 256>>>(Wd);
    k_mma     <<<dim3(NB/128, DICTN/128), 256, MMA_SMEM>>>();
    k_screen32<<<NB, 256, SCR_SMEM>>>();
    k_dead    <<<DICTN/256, 256>>>(nb);
    k_aux     <<<NB, 256, AUX_SMEM>>>();
    k_zero    <<<4096, 256>>>(out + S_OFS);
    k_scatter <<<(NB*K1)/256, 256>>>(out + S_OFS);
    k_decode  <<<NB, 256>>>(Wd, bd, out);
    k_final   <<<1, 256>>>(out + SC_OFS);
}

// round 6
// speedup vs baseline: 2.3188x; 1.7097x over previous
#include <cuda_runtime.h>
#include <cuda_bf16.h>
#include <cstdint>

#define NB    2048
#define DIN   768
#define DOUT  768
#define DICTN 24576
#define K1    32
#define K2    512

#define S_OFS  (NB*DOUT)
#define SC_OFS (S_OFS + NB*DICTN)

// ------------------------- scratch (device globals) -------------------------
__device__ __nv_bfloat16 g_actsb[(size_t)NB*DICTN];  // approx acts, relu'd, bf16
__device__ float g_xe[NB*DIN];                       // exact fp32 x_enc
__device__ __nv_bfloat16 g_ahi[NB*DIN];
__device__ float g_wt [(size_t)DICTN*DIN];           // W_enc^T fp32 [n][k]
__device__ __nv_bfloat16 g_whi[(size_t)DICTN*DIN];   // W_enc^T bf16
__device__ __nv_bfloat16 g_wdh[(size_t)DICTN*DOUT];  // W_dec bf16
__device__ float g_yn[NB*DOUT];
__device__ float g_ymean[NB];
__device__ float g_ystd[NB];
__device__ float g_v32[NB*K1];
__device__ int   g_i32[NB*K1];
__device__ float g_rowl1[NB];
__device__ float g_rowl0[NB];
__device__ float g_rowl2[NB];
__device__ float g_rowaux[NB];
__device__ int   g_colact[DICTN];
__device__ unsigned int g_deadmask[DICTN/32];
__device__ int   g_numdead;
__device__ int   g_deadany;
__device__ float g_vaux[(size_t)NB*K2];
__device__ int   g_iaux[(size_t)NB*K2];
__device__ int   g_cntaux[NB];

// --------------------------- helpers -----------------------------------------
__device__ __forceinline__ uint32_t smem_u32(const void* p) {
    uint32_t a;
    asm("{ .reg .u64 t; cvta.to.shared.u64 t, %1; cvt.u32.u64 %0, t; }"
        : "=r"(a) : "l"(p));
    return a;
}
__device__ __forceinline__ void cpa16(uint32_t dst, const void* src) {
    asm volatile("cp.async.ca.shared.global [%0], [%1], 16;"
                 :: "r"(dst), "l"(src) : "memory");
}
__device__ __forceinline__ void ldm4(uint32_t* r, uint32_t addr) {
    asm volatile("ldmatrix.sync.aligned.m8n8.x4.shared.b16 {%0,%1,%2,%3}, [%4];"
                 : "=r"(r[0]), "=r"(r[1]), "=r"(r[2]), "=r"(r[3]) : "r"(addr));
}
__device__ __forceinline__ void mma16816(float* d, const uint32_t* a,
                                         uint32_t b0, uint32_t b1) {
    asm volatile(
        "mma.sync.aligned.m16n8k16.row.col.f32.bf16.bf16.f32 "
        "{%0,%1,%2,%3}, {%4,%5,%6,%7}, {%8,%9}, {%0,%1,%2,%3};"
        : "+f"(d[0]), "+f"(d[1]), "+f"(d[2]), "+f"(d[3])
        : "r"(a[0]), "r"(a[1]), "r"(a[2]), "r"(a[3]), "r"(b0), "r"(b1));
}
__device__ __forceinline__ float bf_lo(uint32_t w) {
    return __bfloat162float(*(__nv_bfloat16*)&w);
}
__device__ __forceinline__ float bf_hi(uint32_t w) {
    uint16_t h = (uint16_t)(w >> 16);
    return __bfloat162float(*(__nv_bfloat16*)&h);
}

// ------------------------------- init ---------------------------------------
__global__ void k_init() {
    int i = blockIdx.x*blockDim.x + threadIdx.x;
    if (i < DICTN) g_colact[i] = 0;
    if (i == 0) { g_numdead = 0; g_deadany = 0; }
}

// --------------------------- row normalization ------------------------------
__global__ void k_norm(const float* __restrict__ x, const float* __restrict__ y,
                       const float* __restrict__ bdec) {
    int r = blockIdx.x, t = threadIdx.x;
    __shared__ float red[256];

    float x0 = x[r*DIN + t], x1 = x[r*DIN + t + 256], x2 = x[r*DIN + t + 512];
    red[t] = x0 + x1 + x2; __syncthreads();
    for (int o = 128; o > 0; o >>= 1) { if (t < o) red[t] += red[t+o]; __syncthreads(); }
    float m = red[0] * (1.0f/DIN);
    __syncthreads();
    float d0 = x0 - m, d1 = x1 - m, d2 = x2 - m;
    red[t] = d0*d0 + d1*d1 + d2*d2; __syncthreads();
    for (int o = 128; o > 0; o >>= 1) { if (t < o) red[t] += red[t+o]; __syncthreads(); }
    float s = sqrtf(red[0] * (1.0f/(DIN-1)));
    __syncthreads();
    float inv = 1.0f/(s + 1e-5f);
    float e0 = d0*inv - bdec[t];
    float e1 = d1*inv - bdec[t+256];
    float e2 = d2*inv - bdec[t+512];
    g_xe[r*DIN + t]       = e0;
    g_xe[r*DIN + t + 256] = e1;
    g_xe[r*DIN + t + 512] = e2;
    g_ahi[r*DIN + t]       = __float2bfloat16(e0);
    g_ahi[r*DIN + t + 256] = __float2bfloat16(e1);
    g_ahi[r*DIN + t + 512] = __float2bfloat16(e2);

    float y0 = y[r*DOUT + t], y1 = y[r*DOUT + t + 256], y2 = y[r*DOUT + t + 512];
    red[t] = y0 + y1 + y2; __syncthreads();
    for (int o = 128; o > 0; o >>= 1) { if (t < o) red[t] += red[t+o]; __syncthreads(); }
    float my = red[0] * (1.0f/DOUT);
    __syncthreads();
    float f0 = y0 - my, f1 = y1 - my, f2 = y2 - my;
    red[t] = f0*f0 + f1*f1 + f2*f2; __syncthreads();
    for (int o = 128; o > 0; o >>= 1) { if (t < o) red[t] += red[t+o]; __syncthreads(); }
    float sy = sqrtf(red[0] * (1.0f/(DOUT-1)));
    __syncthreads();
    float invy = 1.0f/(sy + 1e-5f);
    g_yn[r*DOUT + t]       = f0*invy;
    g_yn[r*DOUT + t + 256] = f1*invy;
    g_yn[r*DOUT + t + 512] = f2*invy;
    if (t == 0) { g_ymean[r] = my; g_ystd[r] = sy; }
}

// ------------------- W_enc transpose (fp32 + bf16) ---------------------------
__global__ void k_convB(const float* __restrict__ We) {
    __shared__ float tile[32][33];
    int n0 = blockIdx.x*32, k0 = blockIdx.y*32;
    int tx = threadIdx.x, ty = threadIdx.y;
#pragma unroll
    for (int i = 0; i < 4; i++)
        tile[ty + i*8][tx] = We[(size_t)(k0 + ty + i*8)*DICTN + n0 + tx];
    __syncthreads();
#pragma unroll
    for (int i = 0; i < 4; i++) {
        int n = n0 + ty + i*8, k = k0 + tx;
        float v = tile[tx][ty + i*8];
        g_wt[(size_t)n*DIN + k] = v;
        g_whi[(size_t)n*DIN + k] = __float2bfloat16(v);
    }
}

// ------------------- W_dec bf16 copy -----------------------------------------
__global__ void k_convD(const float* __restrict__ Wd) {
    size_t i = (size_t)blockIdx.x*256 + threadIdx.x;
    float4 v = ((const float4*)Wd)[i];
    __nv_bfloat162 p0 = __floats2bfloat162_rn(v.x, v.y);
    __nv_bfloat162 p1 = __floats2bfloat162_rn(v.z, v.w);
    ((__nv_bfloat162*)g_wdh)[i*2]   = p0;
    ((__nv_bfloat162*)g_wdh)[i*2+1] = p1;
}

// ------------------------------ HMMA GEMM ------------------------------------
#define PITCH    80
#define OF_B     10240
#define STG      20480
#define MMA_SMEM (4*STG)
#define NS       (DIN/32)   /* 24 */

__global__ void __launch_bounds__(256, 2) k_mma() {
    extern __shared__ char sm[];
    uint32_t smb = smem_u32(sm);
    int t = threadIdx.x, lid = t & 31, wid = t >> 5;
    int m0 = blockIdx.x * 128, n0 = blockIdx.y * 128;
    int warpM = wid & 1, warpN = wid >> 1;

    float acc[4][4][4];
#pragma unroll
    for (int i = 0; i < 4; i++)
#pragma unroll
        for (int j = 0; j < 4; j++)
#pragma unroll
            for (int q = 0; q < 4; q++) acc[i][j][q] = 0.f;

    auto issue = [&](int s) {
        int k0 = s * 32;
        uint32_t sb = smb + (s & 3) * STG;
#pragma unroll
        for (int c = t; c < 1024; c += 256) {
            int isB = c >> 9;
            int cc = c & 511;
            int row = cc >> 2, ch = cc & 3;
            uint32_t d = sb + isB*OF_B + row*PITCH + ch*16;
            const __nv_bfloat16* src = isB
                ? g_whi + (size_t)(n0+row)*DIN + k0 + ch*8
                : g_ahi + (size_t)(m0+row)*DIN + k0 + ch*8;
            cpa16(d, src);
        }
        asm volatile("cp.async.commit_group;" ::: "memory");
    };

    int sub = lid >> 3, le = lid & 7;
    uint32_t aAddr = smb + (uint32_t)(warpM*64 + (sub&1)*8 + le)*PITCH + (sub>>1)*16;
    uint32_t bAddr = smb + OF_B + (uint32_t)(warpN*32 + (sub>>1)*8 + le)*PITCH + (sub&1)*16;

    issue(0); issue(1); issue(2);
    for (int s = 0; s < NS; ++s) {
        if (s + 3 < NS) {
            issue(s + 3);
            asm volatile("cp.async.wait_group 3;" ::: "memory");
        } else if (s + 2 < NS) {
            asm volatile("cp.async.wait_group 2;" ::: "memory");
        } else if (s + 1 < NS) {
            asm volatile("cp.async.wait_group 1;" ::: "memory");
        } else {
            asm volatile("cp.async.wait_group 0;" ::: "memory");
        }
        __syncthreads();
        uint32_t st = (s & 3) * STG;
#pragma unroll
        for (int kk = 0; kk < 2; ++kk) {
            uint32_t ka = st + kk*32;
            uint32_t ah[4][4], bh[2][4];
#pragma unroll
            for (int mt = 0; mt < 4; ++mt) ldm4(ah[mt], aAddr + ka + mt*(16*PITCH));
#pragma unroll
            for (int bt = 0; bt < 2; ++bt) ldm4(bh[bt], bAddr + ka + bt*(16*PITCH));
#pragma unroll
            for (int mt = 0; mt < 4; ++mt)
#pragma unroll
                for (int nt = 0; nt < 4; ++nt) {
                    int bt = nt >> 1, pr = (nt & 1) * 2;
                    mma16816(acc[mt][nt], ah[mt], bh[bt][pr], bh[bt][pr+1]);
                }
        }
        __syncthreads();
    }

    int rbase = m0 + warpM*64 + (lid >> 2);
    int cbase = n0 + warpN*32 + (lid & 3)*2;
#pragma unroll
    for (int mt = 0; mt < 4; ++mt)
#pragma unroll
        for (int nt = 0; nt < 4; ++nt) {
            int gr = rbase + mt*16, gc = cbase + nt*8;
            __nv_bfloat162 p0 = __floats2bfloat162_rn(fmaxf(acc[mt][nt][0], 0.f),
                                                      fmaxf(acc[mt][nt][1], 0.f));
            __nv_bfloat162 p1 = __floats2bfloat162_rn(fmaxf(acc[mt][nt][2], 0.f),
                                                      fmaxf(acc[mt][nt][3], 0.f));
            *(__nv_bfloat162*)(g_actsb + (size_t)gr*DICTN + gc)     = p0;
            *(__nv_bfloat162*)(g_actsb + (size_t)(gr+8)*DICTN + gc) = p1;
        }
}

// ------------------ top-32: screen (approx) + exact recompute ----------------
// row held in registers (12 x uint4 = 96 bf16 per thread); smem ~25 KB
#define CCAP 256
__global__ void __launch_bounds__(256) k_screen32() {
    __shared__ uint32_t hist[4096];
    __shared__ float xs[DIN];
    __shared__ int csum[256];
    __shared__ int sB, sNc;
    __shared__ int   cidx[CCAP];
    __shared__ float cval[CCAP];
    __shared__ float selv[K1];
    __shared__ int   seli[K1];

    int r = blockIdx.x, t = threadIdx.x;
    uint4 rv[12];
    const uint4* src = (const uint4*)(g_actsb + (size_t)r*DICTN);
#pragma unroll
    for (int i = 0; i < 12; i++) rv[i] = src[t + i*256];
    for (int i = t; i < 4096; i += 256) hist[i] = 0u;
    for (int i = t; i < DIN;  i += 256) xs[i] = g_xe[r*DIN + i];
    if (t < K1) { selv[t] = 0.f; seli[t] = -1; }
    if (t == 0) sNc = 0;
    __syncthreads();
#pragma unroll
    for (int i = 0; i < 12; i++) {
        uint32_t w[4] = {rv[i].x, rv[i].y, rv[i].z, rv[i].w};
#pragma unroll
        for (int h = 0; h < 4; h++) {
            float v0 = bf_lo(w[h]), v1 = bf_hi(w[h]);
            if (v0 > 0.f) {
                int b = (int)(v0 * 256.0f); if (b > 4095) b = 4095;
                atomicAdd(&hist[b], 1u);
            }
            if (v1 > 0.f) {
                int b = (int)(v1 * 256.0f); if (b > 4095) b = 4095;
                atomicAdd(&hist[b], 1u);
            }
        }
    }
    __syncthreads();
    int cs = 0;
#pragma unroll
    for (int u = 0; u < 16; u++) cs += (int)hist[t*16 + u];
    csum[t] = cs; __syncthreads();
    for (int o = 1; o < 256; o <<= 1) {
        int v = (t + o < 256) ? csum[t+o] : 0;
        __syncthreads();
        csum[t] += v;
        __syncthreads();
    }
    if (t == 0) {
        int c = 255;
        while (c > 0 && csum[c] < K1) c--;
        int cum = (c < 255) ? csum[c+1] : 0;
        int b = 0;
        for (int bb = c*16 + 15; bb >= c*16; bb--) {
            cum += (int)hist[bb];
            if (cum >= K1) { b = bb; break; }
        }
        sB = b;
    }
    __syncthreads();
    float thr = (float)sB * (1.0f/256.0f) - 0.06f;
#pragma unroll
    for (int i = 0; i < 12; i++) {
        uint32_t w[4] = {rv[i].x, rv[i].y, rv[i].z, rv[i].w};
        int jb = (t + i*256) * 8;
#pragma unroll
        for (int h = 0; h < 4; h++) {
            float v0 = bf_lo(w[h]), v1 = bf_hi(w[h]);
            if (v0 > 0.f && v0 >= thr) {
                int p = atomicAdd(&sNc, 1);
                if (p < CCAP) cidx[p] = jb + h*2;
            }
            if (v1 > 0.f && v1 >= thr) {
                int p = atomicAdd(&sNc, 1);
                if (p < CCAP) cidx[p] = jb + h*2 + 1;
            }
        }
    }
    __syncthreads();
    int nc = sNc < CCAP ? sNc : CCAP;
    for (int c = (t >> 5); c < nc; c += 8) {      // exact fp32 recompute
        const float* wr = g_wt + (size_t)cidx[c]*DIN;
        float s = 0.f;
        for (int k = (t & 31); k < DIN; k += 32) s = fmaf(xs[k], wr[k], s);
#pragma unroll
        for (int o = 16; o > 0; o >>= 1) s += __shfl_xor_sync(0xffffffffu, s, o);
        if ((t & 31) == 0) cval[c] = s;
    }
    __syncthreads();
    if (t < nc) {
        float v = fmaxf(cval[t], 0.f);
        int idx = cidx[t];
        int rank = 0;
        for (int u = 0; u < nc; ++u) {
            float vu = fmaxf(cval[u], 0.f);
            if (vu > v || (vu == v && cidx[u] < idx)) rank++;
        }
        if (rank < K1) { selv[rank] = v; seli[rank] = idx; }
    }
    __syncthreads();
    if (t < K1) {
        g_v32[r*K1 + t] = selv[t];
        g_i32[r*K1 + t] = seli[t];
        if (selv[t] > 0.f && seli[t] >= 0) g_colact[seli[t]] = 1;
    }
    if (t == 0) {
        float l1 = 0.f, l0 = 0.f;
        for (int q = 0; q < K1; ++q)
            if (selv[q] > 0.f) { l1 += selv[q]; l0 += 1.f; }
        g_rowl1[r] = l1; g_rowl0[r] = l0;
    }
}

// ----------------------- dead-feature bookkeeping ---------------------------
__global__ void k_dead(const float* __restrict__ nb) {
    int c = blockIdx.x*256 + threadIdx.x;
    float nbn = g_colact[c] ? 0.f : nb[c] + 1.f;
    int dead = (nbn >= 100.f) ? 1 : 0;
    unsigned m = __ballot_sync(0xffffffffu, dead);
    if ((threadIdx.x & 31) == 0) g_deadmask[c >> 5] = m;
    if (dead) atomicOr(&g_deadany, 1);
    if (nbn > 100.f) atomicAdd(&g_numdead, 1);
}

// --------------------- aux top-512 per row (dead mask) ----------------------
#define ACAP 1024
__global__ void __launch_bounds__(256) k_aux() {
    __shared__ uint32_t hist[4096];
    __shared__ unsigned int dm[DICTN/32];
    __shared__ int csum[256];
    __shared__ int sB, sNc;
    __shared__ float avv[ACAP];
    __shared__ int   aid[ACAP];

    int r = blockIdx.x, t = threadIdx.x;
    uint4 rv[12];
    const uint4* src = (const uint4*)(g_actsb + (size_t)r*DICTN);
#pragma unroll
    for (int i = 0; i < 12; i++) rv[i] = src[t + i*256];
    for (int i = t; i < 4096; i += 256) hist[i] = 0u;
    for (int i = t; i < DICTN/32; i += 256) dm[i] = g_deadmask[i];
    if (t == 0) sNc = 0;
    __syncthreads();
#pragma unroll
    for (int i = 0; i < 12; i++) {
        uint32_t w[4] = {rv[i].x, rv[i].y, rv[i].z, rv[i].w};
        int jb = (t + i*256) * 8;
#pragma unroll
        for (int h = 0; h < 4; h++) {
            int j0 = jb + h*2, j1 = j0 + 1;
            float v0 = bf_lo(w[h]), v1 = bf_hi(w[h]);
            if (v0 > 0.f && ((dm[j0>>5] >> (j0 & 31)) & 1u)) {
                int b = (int)(v0 * 256.0f); if (b > 4095) b = 4095;
                atomicAdd(&hist[b], 1u);
            }
            if (v1 > 0.f && ((dm[j1>>5] >> (j1 & 31)) & 1u)) {
                int b = (int)(v1 * 256.0f); if (b > 4095) b = 4095;
                atomicAdd(&hist[b], 1u);
            }
        }
    }
    __syncthreads();
    int cs = 0;
#pragma unroll
    for (int u = 0; u < 16; u++) cs += (int)hist[t*16 + u];
    csum[t] = cs; __syncthreads();
    for (int o = 1; o < 256; o <<= 1) {
        int v = (t + o < 256) ? csum[t+o] : 0;
        __syncthreads();
        csum[t] += v;
        __syncthreads();
    }
    if (t == 0) {
        int c = 255;
        while (c > 0 && csum[c] < K2) c--;
        int cum = (c < 255) ? csum[c+1] : 0;
        int b = 0;
        for (int bb = c*16 + 15; bb >= c*16; bb--) {
            cum += (int)hist[bb];
            if (cum >= K2) { b = bb; break; }
        }
        sB = b;
    }
    __syncthreads();
    float thr = (float)sB * (1.0f/256.0f);
#pragma unroll
    for (int i = 0; i < 12; i++) {
        uint32_t w[4] = {rv[i].x, rv[i].y, rv[i].z, rv[i].w};
        int jb = (t + i*256) * 8;
#pragma unroll
        for (int h = 0; h < 4; h++) {
            int j0 = jb + h*2, j1 = j0 + 1;
            float v0 = bf_lo(w[h]), v1 = bf_hi(w[h]);
            if (v0 > 0.f && v0 >= thr && ((dm[j0>>5] >> (j0 & 31)) & 1u)) {
                int p = atomicAdd(&sNc, 1);
                if (p < ACAP) { avv[p] = v0; aid[p] = j0; }
            }
            if (v1 > 0.f && v1 >= thr && ((dm[j1>>5] >> (j1 & 31)) & 1u)) {
                int p = atomicAdd(&sNc, 1);
                if (p < ACAP) { avv[p] = v1; aid[p] = j1; }
            }
        }
    }
    __syncthreads();
    int nc = sNc < ACAP ? sNc : ACAP;
    for (int c = t; c < nc; c += 256) {
        float v = avv[c]; int idx = aid[c];
        int rank = 0;
        for (int u = 0; u < nc; ++u) {
            float vu = avv[u];
            if (vu > v || (vu == v && aid[u] < idx)) rank++;
        }
        if (rank < K2) {
            g_vaux[(size_t)r*K2 + rank] = v;
            g_iaux[(size_t)r*K2 + rank] = idx;
        }
    }
    if (t == 0) g_cntaux[r] = nc < K2 ? nc : K2;
}

// ---------------------- zero + scatter acts_sparse --------------------------
__global__ void k_zero(float* __restrict__ p) {
    size_t i  = (size_t)blockIdx.x*blockDim.x + threadIdx.x;
    size_t n4 = (size_t)NB*DICTN/4;
    float4 z = {0.f, 0.f, 0.f, 0.f};
    for (size_t j = i; j < n4; j += (size_t)gridDim.x*blockDim.x)
        ((float4*)p)[j] = z;
}
__global__ void k_scatter(float* __restrict__ p) {
    int i = blockIdx.x*256 + threadIdx.x;
    if (i >= NB*K1) return;
    int r = i / K1;
    int id = g_i32[i];
    if (id >= 0) p[(size_t)r*DICTN + id] = g_v32[i];
}

// ------------------------ decode + per-row losses ---------------------------
// Warp-specialized: warp w handles q-slice; vector loads; smem per-warp slices.
#define DEC_SMEM (16*DOUT*4)   /* py[8][768] + pa[8][768] = 48 KB */
__global__ void __launch_bounds__(256) k_decode(const float* __restrict__ Wd,
                                                const float* __restrict__ bdec,
                                                float* __restrict__ outy) {
    extern __shared__ float dsm[];
    float* py = dsm;               // [8][768]
    float* pa = dsm + 8*DOUT;      // [8][768]
    __shared__ float sv[K1]; __shared__ int si[K1];
    __shared__ float av[K2]; __shared__ int ai[K2];
    __shared__ float red[256];

    int r = blockIdx.x, t = threadIdx.x, wid = t >> 5, lane = t & 31;
    if (t < K1) { sv[t] = g_v32[r*K1 + t]; si[t] = g_i32[r*K1 + t]; }
    int cnt = g_cntaux[r];
    for (int q = t; q < cnt; q += 256) {
        av[q] = g_vaux[(size_t)r*K2 + q];
        ai[q] = g_iaux[(size_t)r*K2 + q];
    }
    __syncthreads();

    // ---- exact y_pred partials: warp w does q = w*4 .. w*4+3 ----
    float ay[6][4];
#pragma unroll
    for (int i = 0; i < 6; i++)
#pragma unroll
        for (int e = 0; e < 4; e++) ay[i][e] = 0.f;
#pragma unroll
    for (int qq = 0; qq < 4; qq++) {
        int q = wid*4 + qq;
        int id = si[q];
        float v = sv[q];
        if (id >= 0) {
            const float4* wrow = (const float4*)(Wd + (size_t)id*DOUT);
#pragma unroll
            for (int it = 0; it < 6; it++) {
                float4 wv = wrow[it*32 + lane];
                ay[it][0] = fmaf(v, wv.x, ay[it][0]);
                ay[it][1] = fmaf(v, wv.y, ay[it][1]);
                ay[it][2] = fmaf(v, wv.z, ay[it][2]);
                ay[it][3] = fmaf(v, wv.w, ay[it][3]);
            }
        }
    }
#pragma unroll
    for (int it = 0; it < 6; it++) {
        float4 o = {ay[it][0], ay[it][1], ay[it][2], ay[it][3]};
        ((float4*)(py + wid*DOUT + it*128))[lane] = o;
    }

    // ---- aux partials (bf16 weights): warp w does q = w*64 .. ----
    float aa[3][8];
#pragma unroll
    for (int i = 0; i < 3; i++)
#pragma unroll
        for (int e = 0; e < 8; e++) aa[i][e] = 0.f;
    int qs = wid*64, qe = qs + 64 < cnt ? qs + 64 : cnt;
    for (int q = qs; q < qe; q++) {
        float v = av[q];
        const uint4* wrow = (const uint4*)(g_wdh + (size_t)ai[q]*DOUT);
#pragma unroll
        for (int it = 0; it < 3; it++) {
            uint4 wv = wrow[it*32 + lane];
            uint32_t ws[4] = {wv.x, wv.y, wv.z, wv.w};
#pragma unroll
            for (int h = 0; h < 4; h++) {
                aa[it][h*2]   = fmaf(v, bf_lo(ws[h]), aa[it][h*2]);
                aa[it][h*2+1] = fmaf(v, bf_hi(ws[h]), aa[it][h*2+1]);
            }
        }
    }
#pragma unroll
    for (int it = 0; it < 3; it++) {
        float4 o0 = {aa[it][0], aa[it][1], aa[it][2], aa[it][3]};
        float4 o1 = {aa[it][4], aa[it][5], aa[it][6], aa[it][7]};
        ((float4*)(pa + wid*DOUT + it*256))[lane*2]     = o0;
        ((float4*)(pa + wid*DOUT + it*256))[lane*2 + 1] = o1;
    }
    __syncthreads();

    // ---- combine (fixed order), write y_pred_out, per-row losses ----
    float ymean = g_ymean[r], ystd = g_ystd[r];
    float l2p = 0.f, auxp = 0.f;
    for (int d = t; d < DOUT; d += 256) {
        float yp = bdec[d];
#pragma unroll
        for (int w = 0; w < 8; w++) yp += py[w*DOUT + d];
        float ynv = g_yn[r*DOUT + d];
        outy[(size_t)r*DOUT + d] = yp*ystd + ymean;
        float e = yp - ynv;
        l2p += e*e;
        float ya = 0.f;
#pragma unroll
        for (int w = 0; w < 8; w++) ya += pa[w*DOUT + d];
        float ea = ya - (ynv - yp);
        auxp += ea*ea;
    }
    red[t] = l2p; __syncthreads();
    for (int o = 128; o > 0; o >>= 1) { if (t < o) red[t] += red[t+o]; __syncthreads(); }
    if (t == 0) g_rowl2[r] = red[0];
    __syncthreads();
    red[t] = auxp; __syncthreads();
    for (int o = 128; o > 0; o >>= 1) { if (t < o) red[t] += red[t+o]; __syncthreads(); }
    if (t == 0) g_rowaux[r] = red[0];
}

// ------------------------------ finalize -------------------------------------
__global__ void k_final(float* __restrict__ outsc) {
    int t = threadIdx.x;
    __shared__ float red[256];
    __shared__ float res[4];
    const float* arrs[4] = { g_rowl2, g_rowaux, g_rowl1, g_rowl0 };
    for (int a = 0; a < 4; a++) {
        float s = 0.f;
        for (int j = t; j < NB; j += 256) s += arrs[a][j];
        red[t] = s; __syncthreads();
        for (int o = 128; o > 0; o >>= 1) { if (t < o) red[t] += red[t+o]; __syncthreads(); }
        if (t == 0) res[a] = red[0];
        __syncthreads();
    }
    if (t == 0) {
        float l2   = res[0] / (float)(NB*DOUT);
        float auxm = res[1] / (float)(NB*DOUT);
        float l1n  = res[2] / (float)NB;
        float l0   = res[3] / (float)NB;
        float l1l  = 0.001f * l1n;
        float aux  = g_deadany ? 0.03125f * auxm : 0.f;
        outsc[0] = l2 + l1l + aux;
        outsc[1] = l2;
        outsc[2] = l1l;
        outsc[3] = l0;
        outsc[4] = l1n;
        outsc[5] = aux;
        outsc[6] = (float)g_numdead;
    }
}

// ------------------------------- launcher ------------------------------------
extern "C" void kernel_launch(void* const* d_in, const int* in_sizes, int n_in,
                              void* d_out, int out_size) {
    (void)in_sizes; (void)n_in; (void)out_size;
    const float* x  = (const float*)d_in[0];
    const float* y  = (const float*)d_in[1];
    const float* nb = (const float*)d_in[2];
    const float* We = (const float*)d_in[3];
    const float* Wd = (const float*)d_in[4];
    const float* bd = (const float*)d_in[5];
    float* out = (float*)d_out;

    cudaFuncSetAttribute(k_mma, cudaFuncAttributeMaxDynamicSharedMemorySize, MMA_SMEM);
    cudaFuncSetAttribute(k_decode, cudaFuncAttributeMaxDynamicSharedMemorySize, DEC_SMEM);

    k_init    <<<DICTN/256, 256>>>();
    k_norm    <<<NB, 256>>>(x, y, bd);
    k_convB   <<<dim3(DICTN/32, DIN/32), dim3(32, 8)>>>(We);
    k_convD   <<<(DICTN*DOUT/4)/256, 256>>>(Wd);
    k_mma     <<<dim3(NB/128, DICTN/128), 256, MMA_SMEM>>>();
    k_screen32<<<NB, 256>>>();
    k_dead    <<<DICTN/256, 256>>>(nb);
    k_aux     <<<NB, 256>>>();
    k_zero    <<<4096, 256>>>(out + S_OFS);
    k_scatter <<<(NB*K1)/256, 256>>>(out + S_OFS);
    k_decode  <<<NB, 256, DEC_SMEM>>>(Wd, bd, out);
    k_final   <<<1, 256>>>(out + SC_OFS);
}